// round 13
// baseline (speedup 1.0000x reference)
#include <cuda_runtime.h>
#include <cuda_bf16.h>
#include <cuda_fp16.h>
#include <cstdint>

#define NB   4096
#define DDIM 1024
#define OLD  3072

#define NSM       148
#define DIST_GRID (2 * NSM)   // 2 CTAs/SM, persistent
#define PROJ_GRID NSM         // 1 CTA/SM, persistent
#define DIST_NT   1024        // 32x32 tiles of 128x128
#define PROJ_NT   512         // 8(n) x 32(m) x 2(z) tiles

// ---------------- scratch globals (no allocs allowed) ----------------
__device__ __nv_bfloat16 g_xhi[2ull * NB * DDIM];   // input splits (anchor,pos)
__device__ __nv_bfloat16 g_xlo[2ull * NB * DDIM];
__device__ __nv_bfloat16 g_whi[DDIM * DDIM];        // W transposed [n][k], hi
__device__ __nv_bfloat16 g_wlo[DDIM * DDIM];        // W transposed [n][k], lo
__device__ __nv_bfloat16 g_abf[NB * DDIM];          // anchor output bf16
__device__ __nv_bfloat16 g_pbf[NB * DDIM];          // pos output bf16
__device__ float  g_p2[NB];                         // ||pos||^2 (atomic-accumulated)
__device__ __half g_est[(size_t)NB * NB];           // estimated dist (32MB)

__device__ __forceinline__ uint32_t smem_u32(const void* p) {
    uint32_t a;
    asm("{ .reg .u64 t; cvta.to.shared.u64 t, %1; cvt.u32.u64 %0, t; }" : "=r"(a) : "l"(p));
    return a;
}
#define SWZ(o) ((uint32_t)(o) ^ ((((uint32_t)(o)) >> 3) & 0x70u))

// ---------------------------------------------------------------------------
// Split inputs into bf16 hi/lo. 16 floats per thread, 4 upfront loads (MLP=4).
// ---------------------------------------------------------------------------
__global__ __launch_bounds__(256) void split_x_kernel(
    const float* __restrict__ ax, const float* __restrict__ px)
{
    const float* X = blockIdx.y ? px : ax;
    __nv_bfloat16* hi = g_xhi + (size_t)blockIdx.y * NB * DDIM;
    __nv_bfloat16* lo = g_xlo + (size_t)blockIdx.y * NB * DDIM;
    const size_t base = ((size_t)blockIdx.x * 256 + threadIdx.x) * 16;
    float4 v[4];
#pragma unroll
    for (int q = 0; q < 4; ++q)
        v[q] = *reinterpret_cast<const float4*>(X + base + q * 4);
#pragma unroll
    for (int q = 0; q < 2; ++q) {
        float f[8] = {v[q*2].x, v[q*2].y, v[q*2].z, v[q*2].w,
                      v[q*2+1].x, v[q*2+1].y, v[q*2+1].z, v[q*2+1].w};
        __align__(16) __nv_bfloat16 h[8], l[8];
#pragma unroll
        for (int i = 0; i < 8; ++i) {
            h[i] = __float2bfloat16(f[i]);
            l[i] = __float2bfloat16(f[i] - __bfloat162float(h[i]));
        }
        *reinterpret_cast<uint4*>(hi + base + q * 8) = *reinterpret_cast<uint4*>(h);
        *reinterpret_cast<uint4*>(lo + base + q * 8) = *reinterpret_cast<uint4*>(l);
    }
}

// ---------------------------------------------------------------------------
// Transpose + split W: g_whi/g_wlo[n][k] = split(W[k][n])
// ---------------------------------------------------------------------------
__global__ __launch_bounds__(256) void split_w_kernel(const float* __restrict__ W) {
    __shared__ float t[32][33];
    const int k0 = blockIdx.y * 32, n0 = blockIdx.x * 32;
    const int tx = threadIdx.x & 31, ty = threadIdx.x >> 5;  // 32x8
#pragma unroll
    for (int i = 0; i < 4; ++i)
        t[ty + i * 8][tx] = W[(size_t)(k0 + ty + i * 8) * DDIM + n0 + tx];
    __syncthreads();
#pragma unroll
    for (int i = 0; i < 4; ++i) {
        const int n = n0 + ty + i * 8;
        const float v = t[tx][ty + i * 8];
        __nv_bfloat16 h = __float2bfloat16(v);
        __nv_bfloat16 l = __float2bfloat16(v - __bfloat162float(h));
        g_whi[(size_t)n * DDIM + k0 + tx] = h;
        g_wlo[(size_t)n * DDIM + k0 + tx] = l;
    }
}

// ---------------------------------------------------------------------------
// Projection GEMM, bf16x3 HMMA, PERSISTENT CTAs: out = X@W + b
// 128x128 tile, BK=64, cp.async double-buffer flowing across tiles.
// Epilogue accumulates ||pos_row||^2 into g_p2 (z==1).
// ---------------------------------------------------------------------------
#define PT (128 * 128)               // 16KB: one tile (128 rows x 128B)
#define PSMEM_BYTES (8 * PT)         // 4 tiles x 2 stages = 128KB
#define NKC (DDIM / 64)              // 16

__device__ __forceinline__ void proj_tile_coords(int t, size_t& m_base, int& bn) {
    const int z = t >> 8;                  // 0..1
    const int bm = ((t >> 3) & 31) * 128;  // 0..3968
    bn = (t & 7) * 128;                    // 0..896
    m_base = (size_t)z * NB + bm;
}

__device__ __forceinline__ void proj_load_stage(uint32_t ss, size_t m_base,
                                                int bn, int kc, int tid) {
#pragma unroll
    for (int it = 0; it < 4; ++it) {
        int idx = it * 256 + tid;
        int r = idx >> 3, c = idx & 7;
        uint32_t so = SWZ(r * 128 + c * 16);
        const size_t ka = (m_base + r) * DDIM + kc * 64 + c * 8;
        const size_t kb = (size_t)(bn + r) * DDIM + kc * 64 + c * 8;
        asm volatile("cp.async.cg.shared.global [%0], [%1], 16;"
                     :: "r"(ss + so), "l"((const void*)&g_xhi[ka]));
        asm volatile("cp.async.cg.shared.global [%0], [%1], 16;"
                     :: "r"(ss + PT + so), "l"((const void*)&g_xlo[ka]));
        asm volatile("cp.async.cg.shared.global [%0], [%1], 16;"
                     :: "r"(ss + 2 * PT + so), "l"((const void*)&g_whi[kb]));
        asm volatile("cp.async.cg.shared.global [%0], [%1], 16;"
                     :: "r"(ss + 3 * PT + so), "l"((const void*)&g_wlo[kb]));
    }
    asm volatile("cp.async.commit_group;" ::: "memory");
}

__global__ __launch_bounds__(256, 1) void proj_mma_kernel(
    const float* __restrict__ bias, float* __restrict__ out)
{
    extern __shared__ __align__(1024) char smem[];
    const uint32_t sb = smem_u32(smem);
    const int tid = threadIdx.x;
    const int wid = tid >> 5, lane = tid & 31;
    const int m_off = (wid & 3) * 32;
    const int n_off = (wid >> 2) * 64;
    const int mi = lane >> 3;
    const int mr = lane & 7;
    const uint32_t stage[2] = {sb, sb + 4 * PT};
    const int stride = gridDim.x;

    int t = blockIdx.x;
    if (t < PROJ_NT) {
        size_t mb0; int bn0;
        proj_tile_coords(t, mb0, bn0);
        proj_load_stage(stage[0], mb0, bn0, 0, tid);
    }

    for (; t < PROJ_NT; t += stride) {
        size_t m_base; int bn;
        proj_tile_coords(t, m_base, bn);

        float acc[2][8][4];
#pragma unroll
        for (int i = 0; i < 2; ++i)
#pragma unroll
            for (int j = 0; j < 8; ++j)
#pragma unroll
                for (int c = 0; c < 4; ++c) acc[i][j][c] = 0.f;

        for (int kc = 0; kc < NKC; ++kc) {
            const int cur = kc & 1;
            bool have_next;
            if (kc + 1 < NKC) {
                proj_load_stage(stage[cur ^ 1], m_base, bn, kc + 1, tid);
                have_next = true;
            } else if (t + stride < PROJ_NT) {
                size_t mb2; int bn2;
                proj_tile_coords(t + stride, mb2, bn2);
                proj_load_stage(stage[cur ^ 1], mb2, bn2, 0, tid);
                have_next = true;
            } else {
                have_next = false;
            }
            if (have_next) asm volatile("cp.async.wait_group 1;" ::: "memory");
            else           asm volatile("cp.async.wait_group 0;" ::: "memory");
            __syncthreads();
            const uint32_t sAh = stage[cur], sAl = stage[cur] + PT;
            const uint32_t sBh = stage[cur] + 2 * PT, sBl = stage[cur] + 3 * PT;

#pragma unroll
            for (int ks = 0; ks < 4; ++ks) {
                const int arow0 = m_off + ((mi & 1) << 3) + mr;
                const int akb = ks * 32 + ((mi >> 1) << 4);
                uint32_t ah[2][4], al[2][4];
#pragma unroll
                for (int i = 0; i < 2; ++i) {
                    uint32_t off = SWZ((arow0 + i * 16) * 128 + akb);
                    asm volatile(
                        "ldmatrix.sync.aligned.m8n8.x4.shared.b16 {%0,%1,%2,%3}, [%4];"
                        : "=r"(ah[i][0]), "=r"(ah[i][1]), "=r"(ah[i][2]), "=r"(ah[i][3])
                        : "r"(sAh + off));
                    asm volatile(
                        "ldmatrix.sync.aligned.m8n8.x4.shared.b16 {%0,%1,%2,%3}, [%4];"
                        : "=r"(al[i][0]), "=r"(al[i][1]), "=r"(al[i][2]), "=r"(al[i][3])
                        : "r"(sAl + off));
                }
                uint32_t bh[4][4], bl[4][4];
                const int brow0 = n_off + ((mi >> 1) << 3) + mr;
                const int bkb = ks * 32 + ((mi & 1) << 4);
#pragma unroll
                for (int j2 = 0; j2 < 4; ++j2) {
                    uint32_t off = SWZ((brow0 + j2 * 16) * 128 + bkb);
                    asm volatile(
                        "ldmatrix.sync.aligned.m8n8.x4.shared.b16 {%0,%1,%2,%3}, [%4];"
                        : "=r"(bh[j2][0]), "=r"(bh[j2][1]), "=r"(bh[j2][2]), "=r"(bh[j2][3])
                        : "r"(sBh + off));
                    asm volatile(
                        "ldmatrix.sync.aligned.m8n8.x4.shared.b16 {%0,%1,%2,%3}, [%4];"
                        : "=r"(bl[j2][0]), "=r"(bl[j2][1]), "=r"(bl[j2][2]), "=r"(bl[j2][3])
                        : "r"(sBl + off));
                }
#pragma unroll
                for (int i = 0; i < 2; ++i)
#pragma unroll
                    for (int j = 0; j < 8; ++j) {
                        const int q = j >> 1, s = (j & 1) * 2;
#define PROJ_MMA(AF, B0, B1)                                                   \
    asm volatile(                                                              \
        "mma.sync.aligned.m16n8k16.row.col.f32.bf16.bf16.f32 "                 \
        "{%0,%1,%2,%3}, {%4,%5,%6,%7}, {%8,%9}, {%0,%1,%2,%3};"                \
        : "+f"(acc[i][j][0]), "+f"(acc[i][j][1]),                              \
          "+f"(acc[i][j][2]), "+f"(acc[i][j][3])                               \
        : "r"(AF[i][0]), "r"(AF[i][1]), "r"(AF[i][2]), "r"(AF[i][3]),          \
          "r"(B0), "r"(B1))
                        PROJ_MMA(ah, bh[q][s], bh[q][s + 1]);
                        PROJ_MMA(ah, bl[q][s], bl[q][s + 1]);
                        PROJ_MMA(al, bh[q][s], bh[q][s + 1]);
#undef PROJ_MMA
                    }
            }
            __syncthreads();
        }

        // epilogue (next tile's chunk-0 loads already in flight)
        const int z = t >> 8;
        const int bm = ((t >> 3) & 31) * 128;
        const int coloff = z ? DDIM : 0;
        __nv_bfloat16* bf = z ? g_pbf : g_abf;
        const int g = lane >> 2;
        const int c2 = (lane & 3) * 2;
#pragma unroll
        for (int i = 0; i < 2; ++i) {
            float s0 = 0.f, s1 = 0.f;
#pragma unroll
            for (int j = 0; j < 8; ++j) {
                const int ncol = bn + n_off + j * 8 + c2;
                const float b0 = bias[ncol], b1 = bias[ncol + 1];
                const int r0 = bm + m_off + i * 16 + g;
                const int r1 = r0 + 8;
                float v00 = acc[i][j][0] + b0, v01 = acc[i][j][1] + b1;
                float v10 = acc[i][j][2] + b0, v11 = acc[i][j][3] + b1;
                *reinterpret_cast<float2*>(&out[(size_t)r0 * OLD + coloff + ncol]) =
                    make_float2(v00, v01);
                *reinterpret_cast<float2*>(&out[(size_t)r1 * OLD + coloff + ncol]) =
                    make_float2(v10, v11);
                __nv_bfloat162 c0 = __floats2bfloat162_rn(v00, v01);
                __nv_bfloat162 c1 = __floats2bfloat162_rn(v10, v11);
                *reinterpret_cast<uint32_t*>(&bf[(size_t)r0 * DDIM + ncol]) =
                    *reinterpret_cast<uint32_t*>(&c0);
                *reinterpret_cast<uint32_t*>(&bf[(size_t)r1 * DDIM + ncol]) =
                    *reinterpret_cast<uint32_t*>(&c1);
                s0 = fmaf(v00, v00, fmaf(v01, v01, s0));
                s1 = fmaf(v10, v10, fmaf(v11, v11, s1));
            }
            if (z) {
                const int r0 = bm + m_off + i * 16 + g;
                atomicAdd(&g_p2[r0], s0);
                atomicAdd(&g_p2[r0 + 8], s1);
            }
        }
    }
}

// ---------------------------------------------------------------------------
// Phase 1: bf16 mma.sync dist estimate -> half est matrix, PERSISTENT CTAs.
// ---------------------------------------------------------------------------
#define TILE_BYTES (128 * 128)
#define DSMEM_BYTES (4 * TILE_BYTES)

__device__ __forceinline__ void dist_load_stage(uint32_t sA, uint32_t sB,
                                                int bm, int bn, int kc, int tid) {
#pragma unroll
    for (int it = 0; it < 4; ++it) {
        int idx = it * 256 + tid;
        int r = idx >> 3, c = idx & 7;
        uint32_t so = SWZ(r * 128 + c * 16);
        asm volatile("cp.async.cg.shared.global [%0], [%1], 16;"
                     :: "r"(sA + so),
                        "l"((const void*)&g_abf[(size_t)(bm + r) * DDIM + kc * 64 + c * 8]));
        asm volatile("cp.async.cg.shared.global [%0], [%1], 16;"
                     :: "r"(sB + so),
                        "l"((const void*)&g_pbf[(size_t)(bn + r) * DDIM + kc * 64 + c * 8]));
    }
    asm volatile("cp.async.commit_group;" ::: "memory");
}

__global__ __launch_bounds__(256, 2) void dist_est_kernel() {
    extern __shared__ __align__(1024) char smem[];
    const uint32_t sb = smem_u32(smem);
    const int tid = threadIdx.x;
    const int wid = tid >> 5, lane = tid & 31;
    const int m_off = (wid & 3) * 32;
    const int n_off = (wid >> 2) * 64;
    const int mi = lane >> 3;
    const int mr = lane & 7;
    const uint32_t sA[2] = {sb,              sb + 2 * TILE_BYTES};
    const uint32_t sB[2] = {sb + TILE_BYTES, sb + 3 * TILE_BYTES};
    const int stride = gridDim.x;

    int t = blockIdx.x;
    if (t < DIST_NT)
        dist_load_stage(sA[0], sB[0], (t >> 5) * 128, (t & 31) * 128, 0, tid);

    for (; t < DIST_NT; t += stride) {
        const int bm = (t >> 5) * 128;
        const int bn = (t & 31) * 128;

        float acc[2][8][4];
#pragma unroll
        for (int i = 0; i < 2; ++i)
#pragma unroll
            for (int j = 0; j < 8; ++j)
#pragma unroll
                for (int c = 0; c < 4; ++c) acc[i][j][c] = 0.f;

        for (int kc = 0; kc < NKC; ++kc) {
            const int cur = kc & 1;
            bool have_next;
            if (kc + 1 < NKC) {
                dist_load_stage(sA[cur ^ 1], sB[cur ^ 1], bm, bn, kc + 1, tid);
                have_next = true;
            } else if (t + stride < DIST_NT) {
                const int t2 = t + stride;
                dist_load_stage(sA[cur ^ 1], sB[cur ^ 1],
                                (t2 >> 5) * 128, (t2 & 31) * 128, 0, tid);
                have_next = true;
            } else {
                have_next = false;
            }
            if (have_next) asm volatile("cp.async.wait_group 1;" ::: "memory");
            else           asm volatile("cp.async.wait_group 0;" ::: "memory");
            __syncthreads();

#pragma unroll
            for (int ks = 0; ks < 4; ++ks) {
                uint32_t a[2][4];
#pragma unroll
                for (int i = 0; i < 2; ++i) {
                    int row = m_off + i * 16 + ((mi & 1) << 3) + mr;
                    int kb = ks * 32 + ((mi >> 1) << 4);
                    asm volatile(
                        "ldmatrix.sync.aligned.m8n8.x4.shared.b16 {%0,%1,%2,%3}, [%4];"
                        : "=r"(a[i][0]), "=r"(a[i][1]), "=r"(a[i][2]), "=r"(a[i][3])
                        : "r"(sA[cur] + SWZ(row * 128 + kb)));
                }
                uint32_t b[4][4];
#pragma unroll
                for (int j2 = 0; j2 < 4; ++j2) {
                    int row = n_off + j2 * 16 + ((mi >> 1) << 3) + mr;
                    int kb = ks * 32 + ((mi & 1) << 4);
                    asm volatile(
                        "ldmatrix.sync.aligned.m8n8.x4.shared.b16 {%0,%1,%2,%3}, [%4];"
                        : "=r"(b[j2][0]), "=r"(b[j2][1]), "=r"(b[j2][2]), "=r"(b[j2][3])
                        : "r"(sB[cur] + SWZ(row * 128 + kb)));
                }
#pragma unroll
                for (int i = 0; i < 2; ++i)
#pragma unroll
                    for (int j = 0; j < 8; ++j) {
                        const uint32_t b0 = b[j >> 1][(j & 1) * 2];
                        const uint32_t b1 = b[j >> 1][(j & 1) * 2 + 1];
                        asm volatile(
                            "mma.sync.aligned.m16n8k16.row.col.f32.bf16.bf16.f32 "
                            "{%0,%1,%2,%3}, {%4,%5,%6,%7}, {%8,%9}, {%0,%1,%2,%3};"
                            : "+f"(acc[i][j][0]), "+f"(acc[i][j][1]),
                              "+f"(acc[i][j][2]), "+f"(acc[i][j][3])
                            : "r"(a[i][0]), "r"(a[i][1]), "r"(a[i][2]), "r"(a[i][3]),
                              "r"(b0), "r"(b1));
                    }
            }
            __syncthreads();
        }

        const int g = lane >> 2;
        const int c2 = (lane & 3) * 2;
#pragma unroll
        for (int i = 0; i < 2; ++i) {
#pragma unroll
            for (int j = 0; j < 8; ++j) {
                const int ncol = bn + n_off + j * 8 + c2;
                const float p2a = g_p2[ncol];
                const float p2b = g_p2[ncol + 1];
                const int r0 = bm + m_off + i * 16 + g;
                const int r1 = r0 + 8;
                float e00 = fmaf(-2.f, acc[i][j][0], p2a);
                float e01 = fmaf(-2.f, acc[i][j][1], p2b);
                float e10 = fmaf(-2.f, acc[i][j][2], p2a);
                float e11 = fmaf(-2.f, acc[i][j][3], p2b);
                if (ncol == r0) e00 = 65504.f;
                if (ncol + 1 == r0) e01 = 65504.f;
                if (ncol == r1) e10 = 65504.f;
                if (ncol + 1 == r1) e11 = 65504.f;
                *reinterpret_cast<__half2*>(&g_est[(size_t)r0 * NB + ncol]) =
                    __floats2half2_rn(e00, e01);
                *reinterpret_cast<__half2*>(&g_est[(size_t)r1 * NB + ncol]) =
                    __floats2half2_rn(e10, e11);
            }
        }
    }
}

// ---------------------------------------------------------------------------
// Phase 2: refine + gather, 4 rows per block. 8 independent 16B est loads
// issued upfront (MLP=8); exact fp32 dots on candidates within MARGIN;
// deterministic packed min; winner pos rows copied to out in-block.
// ---------------------------------------------------------------------------
#define MARGIN 6.0f
#define RPB 4

__global__ __launch_bounds__(256) void refine_kernel(float* __restrict__ out) {
    const int row0 = blockIdx.x * RPB;
    const int tid = threadIdx.x;
    const int wid = tid >> 5, lid = tid & 31;

    __shared__ float red[RPB][8];
    __shared__ int   cand[RPB][64];
    __shared__ int   ccount[RPB];
    __shared__ int   sidx[RPB];
    __shared__ float arow[RPB][DDIM];

    // issue all 8 est loads upfront (MLP=8)
    uint4 v[RPB][2];
#pragma unroll
    for (int r = 0; r < RPB; ++r) {
        const uint4* e = reinterpret_cast<const uint4*>(&g_est[(size_t)(row0 + r) * NB]);
        v[r][0] = e[tid];
        v[r][1] = e[256 + tid];
    }
    if (tid < RPB) ccount[tid] = 0;

    float lmin[RPB];
#pragma unroll
    for (int r = 0; r < RPB; ++r) {
        float m = 3.0e38f;
        const uint32_t* w0 = reinterpret_cast<const uint32_t*>(&v[r][0]);
        const uint32_t* w1 = reinterpret_cast<const uint32_t*>(&v[r][1]);
#pragma unroll
        for (int q = 0; q < 4; ++q) {
            float2 f0 = __half22float2(*reinterpret_cast<const __half2*>(&w0[q]));
            float2 f1 = __half22float2(*reinterpret_cast<const __half2*>(&w1[q]));
            m = fminf(m, fminf(fminf(f0.x, f0.y), fminf(f1.x, f1.y)));
        }
        lmin[r] = m;
    }
#pragma unroll
    for (int off = 16; off > 0; off >>= 1)
#pragma unroll
        for (int r = 0; r < RPB; ++r)
            lmin[r] = fminf(lmin[r], __shfl_xor_sync(0xFFFFFFFFu, lmin[r], off));
    if (lid == 0)
#pragma unroll
        for (int r = 0; r < RPB; ++r) red[r][wid] = lmin[r];
    __syncthreads();

    float thr[RPB];
#pragma unroll
    for (int r = 0; r < RPB; ++r) {
        float m = red[r][0];
#pragma unroll
        for (int w = 1; w < 8; ++w) m = fminf(m, red[r][w]);
        thr[r] = m + MARGIN;
    }

    // candidate collection
#pragma unroll
    for (int r = 0; r < RPB; ++r) {
        const int row = row0 + r;
        const uint32_t* w0 = reinterpret_cast<const uint32_t*>(&v[r][0]);
        const uint32_t* w1 = reinterpret_cast<const uint32_t*>(&v[r][1]);
#pragma unroll
        for (int q = 0; q < 8; ++q) {
            const float2 f = __half22float2(*reinterpret_cast<const __half2*>(
                q < 4 ? &w0[q] : &w1[q - 4]));
            const int j = (q < 4) ? (tid * 8 + q * 2) : (2048 + tid * 8 + (q - 4) * 2);
            if (f.x <= thr[r] && j != row) {
                int p = atomicAdd(&ccount[r], 1);
                if (p < 64) cand[r][p] = j;
            }
            if (f.y <= thr[r] && j + 1 != row) {
                int p = atomicAdd(&ccount[r], 1);
                if (p < 64) cand[r][p] = j + 1;
            }
        }
    }
#pragma unroll
    for (int r = 0; r < RPB; ++r)
        for (int j = tid; j < DDIM; j += 256)
            arow[r][j] = out[(size_t)(row0 + r) * OLD + j];
    __syncthreads();

    // exact fp32 refine per row
#pragma unroll
    for (int r = 0; r < RPB; ++r) {
        const int row = row0 + r;
        int nc = ccount[r]; if (nc > 64) nc = 64;
        unsigned long long best = ~0ull;
        for (int k = 0; k < nc; ++k) {
            const int j = cand[r][k];
            const float* prow = &out[(size_t)j * OLD + DDIM];
            float s = 0.f;
            for (int tt = tid; tt < DDIM; tt += 256) s = fmaf(arow[r][tt], prow[tt], s);
#pragma unroll
            for (int off = 16; off > 0; off >>= 1)
                s += __shfl_xor_sync(0xFFFFFFFFu, s, off);
            if (lid == 0) red[0][wid] = s;
            __syncthreads();
            if (tid == 0) {
                float dot = 0.f;
#pragma unroll
                for (int w = 0; w < 8; ++w) dot += red[0][w];
                float dist = fmaf(-2.0f, dot, g_p2[j]);
                unsigned long long pk =
                    ((unsigned long long)__float_as_uint(dist) << 32) | (unsigned)j;
                if (pk < best) best = pk;
            }
            __syncthreads();
        }
        if (tid == 0) sidx[r] = (int)(unsigned)(best & 0xFFFFFFFFull);
    }
    __syncthreads();

    // fused gather: out[row, 2048:3072] = pos[argmin]
#pragma unroll
    for (int r = 0; r < RPB; ++r) {
        const int idx = sidx[r];
        const float4* src =
            reinterpret_cast<const float4*>(out + (size_t)idx * OLD + DDIM);
        float4* dst =
            reinterpret_cast<float4*>(out + (size_t)(row0 + r) * OLD + 2 * DDIM);
        dst[tid] = src[tid];
    }
}

// ---------------------------------------------------------------------------
extern "C" void kernel_launch(void* const* d_in, const int* in_sizes, int n_in,
                              void* d_out, int out_size) {
    (void)in_sizes; (void)n_in; (void)out_size;
    const float* ax   = (const float*)d_in[0];
    const float* px   = (const float*)d_in[1];
    const float* W    = (const float*)d_in[2];
    const float* bias = (const float*)d_in[3];
    float* out = (float*)d_out;

    cudaFuncSetAttribute(proj_mma_kernel,
                         cudaFuncAttributeMaxDynamicSharedMemorySize, PSMEM_BYTES);
    cudaFuncSetAttribute(dist_est_kernel,
                         cudaFuncAttributeMaxDynamicSharedMemorySize, DSMEM_BYTES);

    void* p2addr = nullptr;
    cudaGetSymbolAddress(&p2addr, g_p2);
    cudaMemsetAsync(p2addr, 0, NB * sizeof(float));

    split_x_kernel<<<dim3(NB * DDIM / (256 * 16), 2), 256>>>(ax, px);
    split_w_kernel<<<dim3(DDIM / 32, DDIM / 32), 256>>>(W);
    proj_mma_kernel<<<PROJ_GRID, 256, PSMEM_BYTES>>>(bias, out);
    dist_est_kernel<<<DIST_GRID, 256, DSMEM_BYTES>>>();
    refine_kernel<<<NB / RPB, 256>>>(out);
}

// round 14
// speedup vs baseline: 1.0613x; 1.0613x over previous
#include <cuda_runtime.h>
#include <cuda_bf16.h>
#include <cuda_fp16.h>
#include <cstdint>

#define NB   4096
#define DDIM 1024
#define OLD  3072

#define NSM       148
#define PROJ_GRID NSM         // 1 CTA/SM, persistent
#define PROJ_NT   512         // 8(n) x 32(m) x 2(z) tiles

// ---------------- scratch globals (no allocs allowed) ----------------
__device__ __nv_bfloat16 g_xhi[2ull * NB * DDIM];   // input splits (anchor,pos)
__device__ __nv_bfloat16 g_xlo[2ull * NB * DDIM];
__device__ __nv_bfloat16 g_whi[DDIM * DDIM];        // W transposed [n][k], hi
__device__ __nv_bfloat16 g_wlo[DDIM * DDIM];        // W transposed [n][k], lo
__device__ __nv_bfloat16 g_abf[NB * DDIM];          // anchor output bf16
__device__ __nv_bfloat16 g_pbf[NB * DDIM];          // pos output bf16
__device__ float  g_p2[NB];                         // ||pos||^2 (atomic-accumulated)
__device__ __half g_est[(size_t)NB * NB];           // estimated dist (32MB)
__device__ int    g_idx[NB];                        // final argmin

__device__ __forceinline__ uint32_t smem_u32(const void* p) {
    uint32_t a;
    asm("{ .reg .u64 t; cvta.to.shared.u64 t, %1; cvt.u32.u64 %0, t; }" : "=r"(a) : "l"(p));
    return a;
}
#define SWZ(o) ((uint32_t)(o) ^ ((((uint32_t)(o)) >> 3) & 0x70u))

// ---------------------------------------------------------------------------
// Split inputs into bf16 hi/lo. 16 floats per thread, 4 upfront loads (MLP=4).
// ---------------------------------------------------------------------------
__global__ __launch_bounds__(256) void split_x_kernel(
    const float* __restrict__ ax, const float* __restrict__ px)
{
    const float* X = blockIdx.y ? px : ax;
    __nv_bfloat16* hi = g_xhi + (size_t)blockIdx.y * NB * DDIM;
    __nv_bfloat16* lo = g_xlo + (size_t)blockIdx.y * NB * DDIM;
    const size_t base = ((size_t)blockIdx.x * 256 + threadIdx.x) * 16;
    float4 v[4];
#pragma unroll
    for (int q = 0; q < 4; ++q)
        v[q] = *reinterpret_cast<const float4*>(X + base + q * 4);
#pragma unroll
    for (int q = 0; q < 2; ++q) {
        float f[8] = {v[q*2].x, v[q*2].y, v[q*2].z, v[q*2].w,
                      v[q*2+1].x, v[q*2+1].y, v[q*2+1].z, v[q*2+1].w};
        __align__(16) __nv_bfloat16 h[8], l[8];
#pragma unroll
        for (int i = 0; i < 8; ++i) {
            h[i] = __float2bfloat16(f[i]);
            l[i] = __float2bfloat16(f[i] - __bfloat162float(h[i]));
        }
        *reinterpret_cast<uint4*>(hi + base + q * 8) = *reinterpret_cast<uint4*>(h);
        *reinterpret_cast<uint4*>(lo + base + q * 8) = *reinterpret_cast<uint4*>(l);
    }
}

// ---------------------------------------------------------------------------
// Transpose + split W: g_whi/g_wlo[n][k] = split(W[k][n])
// ---------------------------------------------------------------------------
__global__ __launch_bounds__(256) void split_w_kernel(const float* __restrict__ W) {
    __shared__ float t[32][33];
    const int k0 = blockIdx.y * 32, n0 = blockIdx.x * 32;
    const int tx = threadIdx.x & 31, ty = threadIdx.x >> 5;  // 32x8
#pragma unroll
    for (int i = 0; i < 4; ++i)
        t[ty + i * 8][tx] = W[(size_t)(k0 + ty + i * 8) * DDIM + n0 + tx];
    __syncthreads();
#pragma unroll
    for (int i = 0; i < 4; ++i) {
        const int n = n0 + ty + i * 8;
        const float v = t[tx][ty + i * 8];
        __nv_bfloat16 h = __float2bfloat16(v);
        __nv_bfloat16 l = __float2bfloat16(v - __bfloat162float(h));
        g_whi[(size_t)n * DDIM + k0 + tx] = h;
        g_wlo[(size_t)n * DDIM + k0 + tx] = l;
    }
}

// ---------------------------------------------------------------------------
// Projection GEMM, bf16x3 HMMA, PERSISTENT CTAs: out = X@W + b
// 128x128 tile, BK=64, cp.async double-buffer flowing across tiles.
// Epilogue accumulates ||pos_row||^2 into g_p2 (z==1).
// ---------------------------------------------------------------------------
#define PT (128 * 128)               // 16KB: one tile (128 rows x 128B)
#define PSMEM_BYTES (8 * PT)         // 4 tiles x 2 stages = 128KB
#define NKC (DDIM / 64)              // 16

__device__ __forceinline__ void proj_tile_coords(int t, size_t& m_base, int& bn) {
    const int z = t >> 8;                  // 0..1
    const int bm = ((t >> 3) & 31) * 128;  // 0..3968
    bn = (t & 7) * 128;                    // 0..896
    m_base = (size_t)z * NB + bm;
}

__device__ __forceinline__ void proj_load_stage(uint32_t ss, size_t m_base,
                                                int bn, int kc, int tid) {
#pragma unroll
    for (int it = 0; it < 4; ++it) {
        int idx = it * 256 + tid;
        int r = idx >> 3, c = idx & 7;
        uint32_t so = SWZ(r * 128 + c * 16);
        const size_t ka = (m_base + r) * DDIM + kc * 64 + c * 8;
        const size_t kb = (size_t)(bn + r) * DDIM + kc * 64 + c * 8;
        asm volatile("cp.async.cg.shared.global [%0], [%1], 16;"
                     :: "r"(ss + so), "l"((const void*)&g_xhi[ka]));
        asm volatile("cp.async.cg.shared.global [%0], [%1], 16;"
                     :: "r"(ss + PT + so), "l"((const void*)&g_xlo[ka]));
        asm volatile("cp.async.cg.shared.global [%0], [%1], 16;"
                     :: "r"(ss + 2 * PT + so), "l"((const void*)&g_whi[kb]));
        asm volatile("cp.async.cg.shared.global [%0], [%1], 16;"
                     :: "r"(ss + 3 * PT + so), "l"((const void*)&g_wlo[kb]));
    }
    asm volatile("cp.async.commit_group;" ::: "memory");
}

__global__ __launch_bounds__(256, 1) void proj_mma_kernel(
    const float* __restrict__ bias, float* __restrict__ out)
{
    extern __shared__ __align__(1024) char smem[];
    const uint32_t sb = smem_u32(smem);
    const int tid = threadIdx.x;
    const int wid = tid >> 5, lane = tid & 31;
    const int m_off = (wid & 3) * 32;
    const int n_off = (wid >> 2) * 64;
    const int mi = lane >> 3;
    const int mr = lane & 7;
    const uint32_t stage[2] = {sb, sb + 4 * PT};
    const int stride = gridDim.x;

    int t = blockIdx.x;
    if (t < PROJ_NT) {
        size_t mb0; int bn0;
        proj_tile_coords(t, mb0, bn0);
        proj_load_stage(stage[0], mb0, bn0, 0, tid);
    }

    for (; t < PROJ_NT; t += stride) {
        size_t m_base; int bn;
        proj_tile_coords(t, m_base, bn);

        float acc[2][8][4];
#pragma unroll
        for (int i = 0; i < 2; ++i)
#pragma unroll
            for (int j = 0; j < 8; ++j)
#pragma unroll
                for (int c = 0; c < 4; ++c) acc[i][j][c] = 0.f;

        for (int kc = 0; kc < NKC; ++kc) {
            const int cur = kc & 1;
            bool have_next;
            if (kc + 1 < NKC) {
                proj_load_stage(stage[cur ^ 1], m_base, bn, kc + 1, tid);
                have_next = true;
            } else if (t + stride < PROJ_NT) {
                size_t mb2; int bn2;
                proj_tile_coords(t + stride, mb2, bn2);
                proj_load_stage(stage[cur ^ 1], mb2, bn2, 0, tid);
                have_next = true;
            } else {
                have_next = false;
            }
            if (have_next) asm volatile("cp.async.wait_group 1;" ::: "memory");
            else           asm volatile("cp.async.wait_group 0;" ::: "memory");
            __syncthreads();
            const uint32_t sAh = stage[cur], sAl = stage[cur] + PT;
            const uint32_t sBh = stage[cur] + 2 * PT, sBl = stage[cur] + 3 * PT;

#pragma unroll
            for (int ks = 0; ks < 4; ++ks) {
                const int arow0 = m_off + ((mi & 1) << 3) + mr;
                const int akb = ks * 32 + ((mi >> 1) << 4);
                uint32_t ah[2][4], al[2][4];
#pragma unroll
                for (int i = 0; i < 2; ++i) {
                    uint32_t off = SWZ((arow0 + i * 16) * 128 + akb);
                    asm volatile(
                        "ldmatrix.sync.aligned.m8n8.x4.shared.b16 {%0,%1,%2,%3}, [%4];"
                        : "=r"(ah[i][0]), "=r"(ah[i][1]), "=r"(ah[i][2]), "=r"(ah[i][3])
                        : "r"(sAh + off));
                    asm volatile(
                        "ldmatrix.sync.aligned.m8n8.x4.shared.b16 {%0,%1,%2,%3}, [%4];"
                        : "=r"(al[i][0]), "=r"(al[i][1]), "=r"(al[i][2]), "=r"(al[i][3])
                        : "r"(sAl + off));
                }
                uint32_t bh[4][4], bl[4][4];
                const int brow0 = n_off + ((mi >> 1) << 3) + mr;
                const int bkb = ks * 32 + ((mi & 1) << 4);
#pragma unroll
                for (int j2 = 0; j2 < 4; ++j2) {
                    uint32_t off = SWZ((brow0 + j2 * 16) * 128 + bkb);
                    asm volatile(
                        "ldmatrix.sync.aligned.m8n8.x4.shared.b16 {%0,%1,%2,%3}, [%4];"
                        : "=r"(bh[j2][0]), "=r"(bh[j2][1]), "=r"(bh[j2][2]), "=r"(bh[j2][3])
                        : "r"(sBh + off));
                    asm volatile(
                        "ldmatrix.sync.aligned.m8n8.x4.shared.b16 {%0,%1,%2,%3}, [%4];"
                        : "=r"(bl[j2][0]), "=r"(bl[j2][1]), "=r"(bl[j2][2]), "=r"(bl[j2][3])
                        : "r"(sBl + off));
                }
#pragma unroll
                for (int i = 0; i < 2; ++i)
#pragma unroll
                    for (int j = 0; j < 8; ++j) {
                        const int q = j >> 1, s = (j & 1) * 2;
#define PROJ_MMA(AF, B0, B1)                                                   \
    asm volatile(                                                              \
        "mma.sync.aligned.m16n8k16.row.col.f32.bf16.bf16.f32 "                 \
        "{%0,%1,%2,%3}, {%4,%5,%6,%7}, {%8,%9}, {%0,%1,%2,%3};"                \
        : "+f"(acc[i][j][0]), "+f"(acc[i][j][1]),                              \
          "+f"(acc[i][j][2]), "+f"(acc[i][j][3])                               \
        : "r"(AF[i][0]), "r"(AF[i][1]), "r"(AF[i][2]), "r"(AF[i][3]),          \
          "r"(B0), "r"(B1))
                        PROJ_MMA(ah, bh[q][s], bh[q][s + 1]);
                        PROJ_MMA(ah, bl[q][s], bl[q][s + 1]);
                        PROJ_MMA(al, bh[q][s], bh[q][s + 1]);
#undef PROJ_MMA
                    }
            }
            __syncthreads();
        }

        // epilogue (next tile's chunk-0 loads already in flight)
        const int z = t >> 8;
        const int bm = ((t >> 3) & 31) * 128;
        const int coloff = z ? DDIM : 0;
        __nv_bfloat16* bf = z ? g_pbf : g_abf;
        const int g = lane >> 2;
        const int c2 = (lane & 3) * 2;
#pragma unroll
        for (int i = 0; i < 2; ++i) {
            float s0 = 0.f, s1 = 0.f;
#pragma unroll
            for (int j = 0; j < 8; ++j) {
                const int ncol = bn + n_off + j * 8 + c2;
                const float b0 = bias[ncol], b1 = bias[ncol + 1];
                const int r0 = bm + m_off + i * 16 + g;
                const int r1 = r0 + 8;
                float v00 = acc[i][j][0] + b0, v01 = acc[i][j][1] + b1;
                float v10 = acc[i][j][2] + b0, v11 = acc[i][j][3] + b1;
                *reinterpret_cast<float2*>(&out[(size_t)r0 * OLD + coloff + ncol]) =
                    make_float2(v00, v01);
                *reinterpret_cast<float2*>(&out[(size_t)r1 * OLD + coloff + ncol]) =
                    make_float2(v10, v11);
                __nv_bfloat162 c0 = __floats2bfloat162_rn(v00, v01);
                __nv_bfloat162 c1 = __floats2bfloat162_rn(v10, v11);
                *reinterpret_cast<uint32_t*>(&bf[(size_t)r0 * DDIM + ncol]) =
                    *reinterpret_cast<uint32_t*>(&c0);
                *reinterpret_cast<uint32_t*>(&bf[(size_t)r1 * DDIM + ncol]) =
                    *reinterpret_cast<uint32_t*>(&c1);
                s0 = fmaf(v00, v00, fmaf(v01, v01, s0));
                s1 = fmaf(v10, v10, fmaf(v11, v11, s1));
            }
            if (z) {
                const int r0 = bm + m_off + i * 16 + g;
                atomicAdd(&g_p2[r0], s0);
                atomicAdd(&g_p2[r0 + 8], s1);
            }
        }
    }
}

// ---------------------------------------------------------------------------
// Phase 1: bf16 mma.sync dist estimate -> half est matrix.
// NON-persistent (dynamic CTA scheduling balances better than fixed stride):
// grid 32x32, 128x128 tile, BK=64, double-buffered, 2 CTAs/SM.
// ---------------------------------------------------------------------------
#define TILE_BYTES (128 * 128)
#define DSMEM_BYTES (4 * TILE_BYTES)

__device__ __forceinline__ void dist_load_stage(uint32_t sA, uint32_t sB,
                                                int bm, int bn, int kc, int tid) {
#pragma unroll
    for (int it = 0; it < 4; ++it) {
        int idx = it * 256 + tid;
        int r = idx >> 3, c = idx & 7;
        uint32_t so = SWZ(r * 128 + c * 16);
        asm volatile("cp.async.cg.shared.global [%0], [%1], 16;"
                     :: "r"(sA + so),
                        "l"((const void*)&g_abf[(size_t)(bm + r) * DDIM + kc * 64 + c * 8]));
        asm volatile("cp.async.cg.shared.global [%0], [%1], 16;"
                     :: "r"(sB + so),
                        "l"((const void*)&g_pbf[(size_t)(bn + r) * DDIM + kc * 64 + c * 8]));
    }
    asm volatile("cp.async.commit_group;" ::: "memory");
}

__global__ __launch_bounds__(256, 2) void dist_est_kernel() {
    extern __shared__ __align__(1024) char smem[];
    const uint32_t sb = smem_u32(smem);
    const int tid = threadIdx.x;
    const int wid = tid >> 5, lane = tid & 31;
    const int bm = blockIdx.y * 128;
    const int bn = blockIdx.x * 128;
    const int m_off = (wid & 3) * 32;
    const int n_off = (wid >> 2) * 64;

    const uint32_t sA[2] = {sb,              sb + 2 * TILE_BYTES};
    const uint32_t sB[2] = {sb + TILE_BYTES, sb + 3 * TILE_BYTES};

    float acc[2][8][4];
#pragma unroll
    for (int i = 0; i < 2; ++i)
#pragma unroll
        for (int j = 0; j < 8; ++j)
#pragma unroll
            for (int c = 0; c < 4; ++c) acc[i][j][c] = 0.f;

    dist_load_stage(sA[0], sB[0], bm, bn, 0, tid);

    const int mi = lane >> 3;
    const int mr = lane & 7;

    for (int kc = 0; kc < NKC; ++kc) {
        const int cur = kc & 1;
        if (kc + 1 < NKC) {
            dist_load_stage(sA[cur ^ 1], sB[cur ^ 1], bm, bn, kc + 1, tid);
            asm volatile("cp.async.wait_group 1;" ::: "memory");
        } else {
            asm volatile("cp.async.wait_group 0;" ::: "memory");
        }
        __syncthreads();

#pragma unroll
        for (int ks = 0; ks < 4; ++ks) {
            uint32_t a[2][4];
#pragma unroll
            for (int i = 0; i < 2; ++i) {
                int row = m_off + i * 16 + ((mi & 1) << 3) + mr;
                int kb = ks * 32 + ((mi >> 1) << 4);
                asm volatile(
                    "ldmatrix.sync.aligned.m8n8.x4.shared.b16 {%0,%1,%2,%3}, [%4];"
                    : "=r"(a[i][0]), "=r"(a[i][1]), "=r"(a[i][2]), "=r"(a[i][3])
                    : "r"(sA[cur] + SWZ(row * 128 + kb)));
            }
            uint32_t b[4][4];
#pragma unroll
            for (int j2 = 0; j2 < 4; ++j2) {
                int row = n_off + j2 * 16 + ((mi >> 1) << 3) + mr;
                int kb = ks * 32 + ((mi & 1) << 4);
                asm volatile(
                    "ldmatrix.sync.aligned.m8n8.x4.shared.b16 {%0,%1,%2,%3}, [%4];"
                    : "=r"(b[j2][0]), "=r"(b[j2][1]), "=r"(b[j2][2]), "=r"(b[j2][3])
                    : "r"(sB[cur] + SWZ(row * 128 + kb)));
            }
#pragma unroll
            for (int i = 0; i < 2; ++i)
#pragma unroll
                for (int j = 0; j < 8; ++j) {
                    const uint32_t b0 = b[j >> 1][(j & 1) * 2];
                    const uint32_t b1 = b[j >> 1][(j & 1) * 2 + 1];
                    asm volatile(
                        "mma.sync.aligned.m16n8k16.row.col.f32.bf16.bf16.f32 "
                        "{%0,%1,%2,%3}, {%4,%5,%6,%7}, {%8,%9}, {%0,%1,%2,%3};"
                        : "+f"(acc[i][j][0]), "+f"(acc[i][j][1]),
                          "+f"(acc[i][j][2]), "+f"(acc[i][j][3])
                        : "r"(a[i][0]), "r"(a[i][1]), "r"(a[i][2]), "r"(a[i][3]),
                          "r"(b0), "r"(b1));
                }
        }
        __syncthreads();
    }

    const int g = lane >> 2;
    const int c2 = (lane & 3) * 2;
#pragma unroll
    for (int i = 0; i < 2; ++i) {
#pragma unroll
        for (int j = 0; j < 8; ++j) {
            const int ncol = bn + n_off + j * 8 + c2;
            const float p2a = g_p2[ncol];
            const float p2b = g_p2[ncol + 1];
            const int r0 = bm + m_off + i * 16 + g;
            const int r1 = r0 + 8;
            float e00 = fmaf(-2.f, acc[i][j][0], p2a);
            float e01 = fmaf(-2.f, acc[i][j][1], p2b);
            float e10 = fmaf(-2.f, acc[i][j][2], p2a);
            float e11 = fmaf(-2.f, acc[i][j][3], p2b);
            if (ncol == r0) e00 = 65504.f;
            if (ncol + 1 == r0) e01 = 65504.f;
            if (ncol == r1) e10 = 65504.f;
            if (ncol + 1 == r1) e11 = 65504.f;
            *reinterpret_cast<__half2*>(&g_est[(size_t)r0 * NB + ncol]) =
                __floats2half2_rn(e00, e01);
            *reinterpret_cast<__half2*>(&g_est[(size_t)r1 * NB + ncol]) =
                __floats2half2_rn(e10, e11);
        }
    }
}

// ---------------------------------------------------------------------------
// Phase 2: per-row refine — 2 rows per block, exact fp32 distance on
// candidates within MARGIN. Deterministic. (R12 version)
// ---------------------------------------------------------------------------
#define MARGIN 6.0f

__global__ __launch_bounds__(256) void refine_kernel(const float* __restrict__ out) {
    const int rowA = blockIdx.x * 2;
    const int rowB = rowA + 1;
    const int tid = threadIdx.x;
    const int wid = tid >> 5, lid = tid & 31;
    const uint4* eA = reinterpret_cast<const uint4*>(&g_est[(size_t)rowA * NB]);
    const uint4* eB = reinterpret_cast<const uint4*>(&g_est[(size_t)rowB * NB]);

    __shared__ float red[2][8];
    __shared__ int   cand[2][64];
    __shared__ int   ccount[2];
    __shared__ float arow[2][DDIM];

    uint4 vA0 = eA[tid];
    uint4 vA1 = eA[256 + tid];
    uint4 vB0 = eB[tid];
    uint4 vB1 = eB[256 + tid];
    float2 fA[8], fB[8];
    {
        const uint32_t* a0 = reinterpret_cast<const uint32_t*>(&vA0);
        const uint32_t* a1 = reinterpret_cast<const uint32_t*>(&vA1);
        const uint32_t* b0 = reinterpret_cast<const uint32_t*>(&vB0);
        const uint32_t* b1 = reinterpret_cast<const uint32_t*>(&vB1);
#pragma unroll
        for (int q = 0; q < 4; ++q) {
            fA[q]     = __half22float2(*reinterpret_cast<const __half2*>(&a0[q]));
            fA[4 + q] = __half22float2(*reinterpret_cast<const __half2*>(&a1[q]));
            fB[q]     = __half22float2(*reinterpret_cast<const __half2*>(&b0[q]));
            fB[4 + q] = __half22float2(*reinterpret_cast<const __half2*>(&b1[q]));
        }
    }
    float lminA = 3.0e38f, lminB = 3.0e38f;
#pragma unroll
    for (int q = 0; q < 8; ++q) {
        lminA = fminf(lminA, fminf(fA[q].x, fA[q].y));
        lminB = fminf(lminB, fminf(fB[q].x, fB[q].y));
    }
#pragma unroll
    for (int off = 16; off > 0; off >>= 1) {
        lminA = fminf(lminA, __shfl_xor_sync(0xFFFFFFFFu, lminA, off));
        lminB = fminf(lminB, __shfl_xor_sync(0xFFFFFFFFu, lminB, off));
    }
    if (lid == 0) { red[0][wid] = lminA; red[1][wid] = lminB; }
    if (tid == 0) { ccount[0] = 0; ccount[1] = 0; }
    __syncthreads();
    float rowminA = red[0][0], rowminB = red[1][0];
#pragma unroll
    for (int w = 1; w < 8; ++w) {
        rowminA = fminf(rowminA, red[0][w]);
        rowminB = fminf(rowminB, red[1][w]);
    }

    const float thrA = rowminA + MARGIN;
    const float thrB = rowminB + MARGIN;
#pragma unroll
    for (int q = 0; q < 8; ++q) {
        const int j = (q < 4) ? (tid * 8 + q * 2) : (2048 + tid * 8 + (q - 4) * 2);
        if (fA[q].x <= thrA && j != rowA) {
            int p = atomicAdd(&ccount[0], 1);
            if (p < 64) cand[0][p] = j;
        }
        if (fA[q].y <= thrA && j + 1 != rowA) {
            int p = atomicAdd(&ccount[0], 1);
            if (p < 64) cand[0][p] = j + 1;
        }
        if (fB[q].x <= thrB && j != rowB) {
            int p = atomicAdd(&ccount[1], 1);
            if (p < 64) cand[1][p] = j;
        }
        if (fB[q].y <= thrB && j + 1 != rowB) {
            int p = atomicAdd(&ccount[1], 1);
            if (p < 64) cand[1][p] = j + 1;
        }
    }
    for (int j = tid; j < DDIM; j += 256) {
        arow[0][j] = out[(size_t)rowA * OLD + j];
        arow[1][j] = out[(size_t)rowB * OLD + j];
    }
    __syncthreads();

#pragma unroll
    for (int r = 0; r < 2; ++r) {
        const int row = rowA + r;
        int nc = ccount[r]; if (nc > 64) nc = 64;
        unsigned long long best = ~0ull;
        for (int k = 0; k < nc; ++k) {
            const int j = cand[r][k];
            const float* prow = &out[(size_t)j * OLD + DDIM];
            float s = 0.f;
            for (int tt = tid; tt < DDIM; tt += 256) s = fmaf(arow[r][tt], prow[tt], s);
#pragma unroll
            for (int off = 16; off > 0; off >>= 1)
                s += __shfl_xor_sync(0xFFFFFFFFu, s, off);
            if (lid == 0) red[0][wid] = s;
            __syncthreads();
            if (tid == 0) {
                float dot = 0.f;
#pragma unroll
                for (int w = 0; w < 8; ++w) dot += red[0][w];
                float dist = fmaf(-2.0f, dot, g_p2[j]);
                unsigned long long pk =
                    ((unsigned long long)__float_as_uint(dist) << 32) | (unsigned)j;
                if (pk < best) best = pk;
            }
            __syncthreads();
        }
        if (tid == 0) g_idx[row] = (int)(unsigned)(best & 0xFFFFFFFFull);
    }
}

// ---------------------------------------------------------------------------
// Gather hard negatives: out[:, 2048:3072] = pos[argmin]
// ---------------------------------------------------------------------------
__global__ __launch_bounds__(256) void gather_kernel(float* __restrict__ out) {
    const int row = blockIdx.x;
    const int idx = g_idx[row];
    const float4* src = reinterpret_cast<const float4*>(out + (size_t)idx * OLD + DDIM);
    float4* dst = reinterpret_cast<float4*>(out + (size_t)row * OLD + 2 * DDIM);
    dst[threadIdx.x] = src[threadIdx.x];
}

// ---------------------------------------------------------------------------
extern "C" void kernel_launch(void* const* d_in, const int* in_sizes, int n_in,
                              void* d_out, int out_size) {
    (void)in_sizes; (void)n_in; (void)out_size;
    const float* ax   = (const float*)d_in[0];
    const float* px   = (const float*)d_in[1];
    const float* W    = (const float*)d_in[2];
    const float* bias = (const float*)d_in[3];
    float* out = (float*)d_out;

    cudaFuncSetAttribute(proj_mma_kernel,
                         cudaFuncAttributeMaxDynamicSharedMemorySize, PSMEM_BYTES);
    cudaFuncSetAttribute(dist_est_kernel,
                         cudaFuncAttributeMaxDynamicSharedMemorySize, DSMEM_BYTES);

    void* p2addr = nullptr;
    cudaGetSymbolAddress(&p2addr, g_p2);
    cudaMemsetAsync(p2addr, 0, NB * sizeof(float));

    split_x_kernel<<<dim3(NB * DDIM / (256 * 16), 2), 256>>>(ax, px);
    split_w_kernel<<<dim3(DDIM / 32, DDIM / 32), 256>>>(W);
    proj_mma_kernel<<<PROJ_GRID, 256, PSMEM_BYTES>>>(bias, out);
    dist_est_kernel<<<dim3(NB / 128, NB / 128), 256, DSMEM_BYTES>>>();
    refine_kernel<<<NB / 2, 256>>>(out);
    gather_kernel<<<NB, 256>>>(out);
}

// round 15
// speedup vs baseline: 1.0664x; 1.0049x over previous
#include <cuda_runtime.h>
#include <cuda_bf16.h>
#include <cuda_fp16.h>
#include <cstdint>

#define NB   4096
#define DDIM 1024
#define OLD  3072

#define NSM       148
#define DIST_GRID (2 * NSM)   // 2 CTAs/SM, persistent
#define PROJ_GRID NSM         // 1 CTA/SM, persistent
#define DIST_NT   1024        // 32x32 tiles of 128x128
#define PROJ_NT   512         // 8(n) x 32(m) x 2(z) tiles

// ---------------- scratch globals (no allocs allowed) ----------------
__device__ __nv_bfloat16 g_xhi[2ull * NB * DDIM];   // input splits (anchor,pos)
__device__ __nv_bfloat16 g_xlo[2ull * NB * DDIM];
__device__ __nv_bfloat16 g_whi[DDIM * DDIM];        // W transposed [n][k], hi
__device__ __nv_bfloat16 g_wlo[DDIM * DDIM];        // W transposed [n][k], lo
__device__ __nv_bfloat16 g_abf[NB * DDIM];          // anchor output bf16
__device__ __nv_bfloat16 g_pbf[NB * DDIM];          // pos output bf16
__device__ float  g_p2[NB];                         // ||pos||^2 (atomic-accumulated)
__device__ __half g_est[(size_t)NB * NB];           // estimated dist (32MB)
__device__ int    g_idx[NB];                        // final argmin

__device__ __forceinline__ uint32_t smem_u32(const void* p) {
    uint32_t a;
    asm("{ .reg .u64 t; cvta.to.shared.u64 t, %1; cvt.u32.u64 %0, t; }" : "=r"(a) : "l"(p));
    return a;
}
#define SWZ(o) ((uint32_t)(o) ^ ((((uint32_t)(o)) >> 3) & 0x70u))

// ---------------------------------------------------------------------------
// Split inputs into bf16 hi/lo. 16 floats per thread, 4 upfront loads (MLP=4).
// ---------------------------------------------------------------------------
__global__ __launch_bounds__(256) void split_x_kernel(
    const float* __restrict__ ax, const float* __restrict__ px)
{
    const float* X = blockIdx.y ? px : ax;
    __nv_bfloat16* hi = g_xhi + (size_t)blockIdx.y * NB * DDIM;
    __nv_bfloat16* lo = g_xlo + (size_t)blockIdx.y * NB * DDIM;
    const size_t base = ((size_t)blockIdx.x * 256 + threadIdx.x) * 16;
    float4 v[4];
#pragma unroll
    for (int q = 0; q < 4; ++q)
        v[q] = *reinterpret_cast<const float4*>(X + base + q * 4);
#pragma unroll
    for (int q = 0; q < 2; ++q) {
        float f[8] = {v[q*2].x, v[q*2].y, v[q*2].z, v[q*2].w,
                      v[q*2+1].x, v[q*2+1].y, v[q*2+1].z, v[q*2+1].w};
        __align__(16) __nv_bfloat16 h[8], l[8];
#pragma unroll
        for (int i = 0; i < 8; ++i) {
            h[i] = __float2bfloat16(f[i]);
            l[i] = __float2bfloat16(f[i] - __bfloat162float(h[i]));
        }
        *reinterpret_cast<uint4*>(hi + base + q * 8) = *reinterpret_cast<uint4*>(h);
        *reinterpret_cast<uint4*>(lo + base + q * 8) = *reinterpret_cast<uint4*>(l);
    }
}

// ---------------------------------------------------------------------------
// Transpose + split W: g_whi/g_wlo[n][k] = split(W[k][n])
// ---------------------------------------------------------------------------
__global__ __launch_bounds__(256) void split_w_kernel(const float* __restrict__ W) {
    __shared__ float t[32][33];
    const int k0 = blockIdx.y * 32, n0 = blockIdx.x * 32;
    const int tx = threadIdx.x & 31, ty = threadIdx.x >> 5;  // 32x8
#pragma unroll
    for (int i = 0; i < 4; ++i)
        t[ty + i * 8][tx] = W[(size_t)(k0 + ty + i * 8) * DDIM + n0 + tx];
    __syncthreads();
#pragma unroll
    for (int i = 0; i < 4; ++i) {
        const int n = n0 + ty + i * 8;
        const float v = t[tx][ty + i * 8];
        __nv_bfloat16 h = __float2bfloat16(v);
        __nv_bfloat16 l = __float2bfloat16(v - __bfloat162float(h));
        g_whi[(size_t)n * DDIM + k0 + tx] = h;
        g_wlo[(size_t)n * DDIM + k0 + tx] = l;
    }
}

// ---------------------------------------------------------------------------
// Projection GEMM, bf16x3 HMMA, PERSISTENT CTAs: out = X@W + b
// 128x128 tile, BK=64, cp.async double-buffer flowing across tiles.
// Epilogue accumulates ||pos_row||^2 into g_p2 (z==1).
// ---------------------------------------------------------------------------
#define PT (128 * 128)               // 16KB: one tile (128 rows x 128B)
#define PSMEM_BYTES (8 * PT)         // 4 tiles x 2 stages = 128KB
#define NKC (DDIM / 64)              // 16

__device__ __forceinline__ void proj_tile_coords(int t, size_t& m_base, int& bn) {
    const int z = t >> 8;                  // 0..1
    const int bm = ((t >> 3) & 31) * 128;  // 0..3968
    bn = (t & 7) * 128;                    // 0..896
    m_base = (size_t)z * NB + bm;
}

__device__ __forceinline__ void proj_load_stage(uint32_t ss, size_t m_base,
                                                int bn, int kc, int tid) {
#pragma unroll
    for (int it = 0; it < 4; ++it) {
        int idx = it * 256 + tid;
        int r = idx >> 3, c = idx & 7;
        uint32_t so = SWZ(r * 128 + c * 16);
        const size_t ka = (m_base + r) * DDIM + kc * 64 + c * 8;
        const size_t kb = (size_t)(bn + r) * DDIM + kc * 64 + c * 8;
        asm volatile("cp.async.cg.shared.global [%0], [%1], 16;"
                     :: "r"(ss + so), "l"((const void*)&g_xhi[ka]));
        asm volatile("cp.async.cg.shared.global [%0], [%1], 16;"
                     :: "r"(ss + PT + so), "l"((const void*)&g_xlo[ka]));
        asm volatile("cp.async.cg.shared.global [%0], [%1], 16;"
                     :: "r"(ss + 2 * PT + so), "l"((const void*)&g_whi[kb]));
        asm volatile("cp.async.cg.shared.global [%0], [%1], 16;"
                     :: "r"(ss + 3 * PT + so), "l"((const void*)&g_wlo[kb]));
    }
    asm volatile("cp.async.commit_group;" ::: "memory");
}

__global__ __launch_bounds__(256, 1) void proj_mma_kernel(
    const float* __restrict__ bias, float* __restrict__ out)
{
    extern __shared__ __align__(1024) char smem[];
    const uint32_t sb = smem_u32(smem);
    const int tid = threadIdx.x;
    const int wid = tid >> 5, lane = tid & 31;
    const int m_off = (wid & 3) * 32;
    const int n_off = (wid >> 2) * 64;
    const int mi = lane >> 3;
    const int mr = lane & 7;
    const uint32_t stage[2] = {sb, sb + 4 * PT};
    const int stride = gridDim.x;

    int t = blockIdx.x;
    if (t < PROJ_NT) {
        size_t mb0; int bn0;
        proj_tile_coords(t, mb0, bn0);
        proj_load_stage(stage[0], mb0, bn0, 0, tid);
    }

    for (; t < PROJ_NT; t += stride) {
        size_t m_base; int bn;
        proj_tile_coords(t, m_base, bn);

        float acc[2][8][4];
#pragma unroll
        for (int i = 0; i < 2; ++i)
#pragma unroll
            for (int j = 0; j < 8; ++j)
#pragma unroll
                for (int c = 0; c < 4; ++c) acc[i][j][c] = 0.f;

        for (int kc = 0; kc < NKC; ++kc) {
            const int cur = kc & 1;
            bool have_next;
            if (kc + 1 < NKC) {
                proj_load_stage(stage[cur ^ 1], m_base, bn, kc + 1, tid);
                have_next = true;
            } else if (t + stride < PROJ_NT) {
                size_t mb2; int bn2;
                proj_tile_coords(t + stride, mb2, bn2);
                proj_load_stage(stage[cur ^ 1], mb2, bn2, 0, tid);
                have_next = true;
            } else {
                have_next = false;
            }
            if (have_next) asm volatile("cp.async.wait_group 1;" ::: "memory");
            else           asm volatile("cp.async.wait_group 0;" ::: "memory");
            __syncthreads();
            const uint32_t sAh = stage[cur], sAl = stage[cur] + PT;
            const uint32_t sBh = stage[cur] + 2 * PT, sBl = stage[cur] + 3 * PT;

#pragma unroll
            for (int ks = 0; ks < 4; ++ks) {
                const int arow0 = m_off + ((mi & 1) << 3) + mr;
                const int akb = ks * 32 + ((mi >> 1) << 4);
                uint32_t ah[2][4], al[2][4];
#pragma unroll
                for (int i = 0; i < 2; ++i) {
                    uint32_t off = SWZ((arow0 + i * 16) * 128 + akb);
                    asm volatile(
                        "ldmatrix.sync.aligned.m8n8.x4.shared.b16 {%0,%1,%2,%3}, [%4];"
                        : "=r"(ah[i][0]), "=r"(ah[i][1]), "=r"(ah[i][2]), "=r"(ah[i][3])
                        : "r"(sAh + off));
                    asm volatile(
                        "ldmatrix.sync.aligned.m8n8.x4.shared.b16 {%0,%1,%2,%3}, [%4];"
                        : "=r"(al[i][0]), "=r"(al[i][1]), "=r"(al[i][2]), "=r"(al[i][3])
                        : "r"(sAl + off));
                }
                uint32_t bh[4][4], bl[4][4];
                const int brow0 = n_off + ((mi >> 1) << 3) + mr;
                const int bkb = ks * 32 + ((mi & 1) << 4);
#pragma unroll
                for (int j2 = 0; j2 < 4; ++j2) {
                    uint32_t off = SWZ((brow0 + j2 * 16) * 128 + bkb);
                    asm volatile(
                        "ldmatrix.sync.aligned.m8n8.x4.shared.b16 {%0,%1,%2,%3}, [%4];"
                        : "=r"(bh[j2][0]), "=r"(bh[j2][1]), "=r"(bh[j2][2]), "=r"(bh[j2][3])
                        : "r"(sBh + off));
                    asm volatile(
                        "ldmatrix.sync.aligned.m8n8.x4.shared.b16 {%0,%1,%2,%3}, [%4];"
                        : "=r"(bl[j2][0]), "=r"(bl[j2][1]), "=r"(bl[j2][2]), "=r"(bl[j2][3])
                        : "r"(sBl + off));
                }
#pragma unroll
                for (int i = 0; i < 2; ++i)
#pragma unroll
                    for (int j = 0; j < 8; ++j) {
                        const int q = j >> 1, s = (j & 1) * 2;
#define PROJ_MMA(AF, B0, B1)                                                   \
    asm volatile(                                                              \
        "mma.sync.aligned.m16n8k16.row.col.f32.bf16.bf16.f32 "                 \
        "{%0,%1,%2,%3}, {%4,%5,%6,%7}, {%8,%9}, {%0,%1,%2,%3};"                \
        : "+f"(acc[i][j][0]), "+f"(acc[i][j][1]),                              \
          "+f"(acc[i][j][2]), "+f"(acc[i][j][3])                               \
        : "r"(AF[i][0]), "r"(AF[i][1]), "r"(AF[i][2]), "r"(AF[i][3]),          \
          "r"(B0), "r"(B1))
                        PROJ_MMA(ah, bh[q][s], bh[q][s + 1]);
                        PROJ_MMA(ah, bl[q][s], bl[q][s + 1]);
                        PROJ_MMA(al, bh[q][s], bh[q][s + 1]);
#undef PROJ_MMA
                    }
            }
            __syncthreads();
        }

        // epilogue (next tile's chunk-0 loads already in flight)
        const int z = t >> 8;
        const int bm = ((t >> 3) & 31) * 128;
        const int coloff = z ? DDIM : 0;
        __nv_bfloat16* bf = z ? g_pbf : g_abf;
        const int g = lane >> 2;
        const int c2 = (lane & 3) * 2;
#pragma unroll
        for (int i = 0; i < 2; ++i) {
            float s0 = 0.f, s1 = 0.f;
#pragma unroll
            for (int j = 0; j < 8; ++j) {
                const int ncol = bn + n_off + j * 8 + c2;
                const float b0 = bias[ncol], b1 = bias[ncol + 1];
                const int r0 = bm + m_off + i * 16 + g;
                const int r1 = r0 + 8;
                float v00 = acc[i][j][0] + b0, v01 = acc[i][j][1] + b1;
                float v10 = acc[i][j][2] + b0, v11 = acc[i][j][3] + b1;
                *reinterpret_cast<float2*>(&out[(size_t)r0 * OLD + coloff + ncol]) =
                    make_float2(v00, v01);
                *reinterpret_cast<float2*>(&out[(size_t)r1 * OLD + coloff + ncol]) =
                    make_float2(v10, v11);
                __nv_bfloat162 c0 = __floats2bfloat162_rn(v00, v01);
                __nv_bfloat162 c1 = __floats2bfloat162_rn(v10, v11);
                *reinterpret_cast<uint32_t*>(&bf[(size_t)r0 * DDIM + ncol]) =
                    *reinterpret_cast<uint32_t*>(&c0);
                *reinterpret_cast<uint32_t*>(&bf[(size_t)r1 * DDIM + ncol]) =
                    *reinterpret_cast<uint32_t*>(&c1);
                s0 = fmaf(v00, v00, fmaf(v01, v01, s0));
                s1 = fmaf(v10, v10, fmaf(v11, v11, s1));
            }
            if (z) {
                const int r0 = bm + m_off + i * 16 + g;
                atomicAdd(&g_p2[r0], s0);
                atomicAdd(&g_p2[r0 + 8], s1);
            }
        }
    }
}

// ---------------------------------------------------------------------------
// Phase 1: bf16 mma.sync dist estimate -> half est matrix, PERSISTENT CTAs
// with BLOCKED (contiguous) tile ranges: CTA c gets tiles [start, start+cnt).
// Consecutive tiles share the same A panel (row-major tile order) -> L2-hot.
// ---------------------------------------------------------------------------
#define TILE_BYTES (128 * 128)
#define DSMEM_BYTES (4 * TILE_BYTES)

__device__ __forceinline__ void dist_load_stage(uint32_t sA, uint32_t sB,
                                                int bm, int bn, int kc, int tid) {
#pragma unroll
    for (int it = 0; it < 4; ++it) {
        int idx = it * 256 + tid;
        int r = idx >> 3, c = idx & 7;
        uint32_t so = SWZ(r * 128 + c * 16);
        asm volatile("cp.async.cg.shared.global [%0], [%1], 16;"
                     :: "r"(sA + so),
                        "l"((const void*)&g_abf[(size_t)(bm + r) * DDIM + kc * 64 + c * 8]));
        asm volatile("cp.async.cg.shared.global [%0], [%1], 16;"
                     :: "r"(sB + so),
                        "l"((const void*)&g_pbf[(size_t)(bn + r) * DDIM + kc * 64 + c * 8]));
    }
    asm volatile("cp.async.commit_group;" ::: "memory");
}

__global__ __launch_bounds__(256, 2) void dist_est_kernel() {
    extern __shared__ __align__(1024) char smem[];
    const uint32_t sb = smem_u32(smem);
    const int tid = threadIdx.x;
    const int wid = tid >> 5, lane = tid & 31;
    const int m_off = (wid & 3) * 32;
    const int n_off = (wid >> 2) * 64;
    const int mi = lane >> 3;
    const int mr = lane & 7;
    const uint32_t sA[2] = {sb,              sb + 2 * TILE_BYTES};
    const uint32_t sB[2] = {sb + TILE_BYTES, sb + 3 * TILE_BYTES};

    // blocked partition: first rem CTAs get q+1 tiles, rest q, contiguous
    const int q   = DIST_NT / DIST_GRID;          // 3
    const int rem = DIST_NT - q * DIST_GRID;      // 136
    const int c   = blockIdx.x;
    const int start = (c < rem) ? c * (q + 1) : rem * (q + 1) + (c - rem) * q;
    const int cnt   = (c < rem) ? (q + 1) : q;
    const int end   = start + cnt;

    int buf = 0;  // double-buffer parity carried across tiles
    dist_load_stage(sA[0], sB[0], (start >> 5) * 128, (start & 31) * 128, 0, tid);

    for (int t = start; t < end; ++t) {
        const int bm = (t >> 5) * 128;
        const int bn = (t & 31) * 128;

        float acc[2][8][4];
#pragma unroll
        for (int i = 0; i < 2; ++i)
#pragma unroll
            for (int j = 0; j < 8; ++j)
#pragma unroll
                for (int cc = 0; cc < 4; ++cc) acc[i][j][cc] = 0.f;

        for (int kc = 0; kc < NKC; ++kc) {
            const int cur = buf;
            bool have_next;
            if (kc + 1 < NKC) {
                dist_load_stage(sA[cur ^ 1], sB[cur ^ 1], bm, bn, kc + 1, tid);
                have_next = true;
            } else if (t + 1 < end) {
                const int t2 = t + 1;
                dist_load_stage(sA[cur ^ 1], sB[cur ^ 1],
                                (t2 >> 5) * 128, (t2 & 31) * 128, 0, tid);
                have_next = true;
            } else {
                have_next = false;
            }
            if (have_next) asm volatile("cp.async.wait_group 1;" ::: "memory");
            else           asm volatile("cp.async.wait_group 0;" ::: "memory");
            __syncthreads();

#pragma unroll
            for (int ks = 0; ks < 4; ++ks) {
                uint32_t a[2][4];
#pragma unroll
                for (int i = 0; i < 2; ++i) {
                    int row = m_off + i * 16 + ((mi & 1) << 3) + mr;
                    int kb = ks * 32 + ((mi >> 1) << 4);
                    asm volatile(
                        "ldmatrix.sync.aligned.m8n8.x4.shared.b16 {%0,%1,%2,%3}, [%4];"
                        : "=r"(a[i][0]), "=r"(a[i][1]), "=r"(a[i][2]), "=r"(a[i][3])
                        : "r"(sA[cur] + SWZ(row * 128 + kb)));
                }
                uint32_t b[4][4];
#pragma unroll
                for (int j2 = 0; j2 < 4; ++j2) {
                    int row = n_off + j2 * 16 + ((mi >> 1) << 3) + mr;
                    int kb = ks * 32 + ((mi & 1) << 4);
                    asm volatile(
                        "ldmatrix.sync.aligned.m8n8.x4.shared.b16 {%0,%1,%2,%3}, [%4];"
                        : "=r"(b[j2][0]), "=r"(b[j2][1]), "=r"(b[j2][2]), "=r"(b[j2][3])
                        : "r"(sB[cur] + SWZ(row * 128 + kb)));
                }
#pragma unroll
                for (int i = 0; i < 2; ++i)
#pragma unroll
                    for (int j = 0; j < 8; ++j) {
                        const uint32_t b0 = b[j >> 1][(j & 1) * 2];
                        const uint32_t b1 = b[j >> 1][(j & 1) * 2 + 1];
                        asm volatile(
                            "mma.sync.aligned.m16n8k16.row.col.f32.bf16.bf16.f32 "
                            "{%0,%1,%2,%3}, {%4,%5,%6,%7}, {%8,%9}, {%0,%1,%2,%3};"
                            : "+f"(acc[i][j][0]), "+f"(acc[i][j][1]),
                              "+f"(acc[i][j][2]), "+f"(acc[i][j][3])
                            : "r"(a[i][0]), "r"(a[i][1]), "r"(a[i][2]), "r"(a[i][3]),
                              "r"(b0), "r"(b1));
                    }
            }
            __syncthreads();
            buf ^= 1;
        }

        // epilogue (next tile's chunk-0 loads already in flight)
        const int g = lane >> 2;
        const int c2 = (lane & 3) * 2;
#pragma unroll
        for (int i = 0; i < 2; ++i) {
#pragma unroll
            for (int j = 0; j < 8; ++j) {
                const int ncol = bn + n_off + j * 8 + c2;
                const float p2a = g_p2[ncol];
                const float p2b = g_p2[ncol + 1];
                const int r0 = bm + m_off + i * 16 + g;
                const int r1 = r0 + 8;
                float e00 = fmaf(-2.f, acc[i][j][0], p2a);
                float e01 = fmaf(-2.f, acc[i][j][1], p2b);
                float e10 = fmaf(-2.f, acc[i][j][2], p2a);
                float e11 = fmaf(-2.f, acc[i][j][3], p2b);
                if (ncol == r0) e00 = 65504.f;
                if (ncol + 1 == r0) e01 = 65504.f;
                if (ncol == r1) e10 = 65504.f;
                if (ncol + 1 == r1) e11 = 65504.f;
                *reinterpret_cast<__half2*>(&g_est[(size_t)r0 * NB + ncol]) =
                    __floats2half2_rn(e00, e01);
                *reinterpret_cast<__half2*>(&g_est[(size_t)r1 * NB + ncol]) =
                    __floats2half2_rn(e10, e11);
            }
        }
    }
}

// ---------------------------------------------------------------------------
// Phase 2: per-row refine — 2 rows per block, exact fp32 distance on
// candidates within MARGIN. Deterministic. (R12 version)
// ---------------------------------------------------------------------------
#define MARGIN 6.0f

__global__ __launch_bounds__(256) void refine_kernel(const float* __restrict__ out) {
    const int rowA = blockIdx.x * 2;
    const int rowB = rowA + 1;
    const int tid = threadIdx.x;
    const int wid = tid >> 5, lid = tid & 31;
    const uint4* eA = reinterpret_cast<const uint4*>(&g_est[(size_t)rowA * NB]);
    const uint4* eB = reinterpret_cast<const uint4*>(&g_est[(size_t)rowB * NB]);

    __shared__ float red[2][8];
    __shared__ int   cand[2][64];
    __shared__ int   ccount[2];
    __shared__ float arow[2][DDIM];

    uint4 vA0 = eA[tid];
    uint4 vA1 = eA[256 + tid];
    uint4 vB0 = eB[tid];
    uint4 vB1 = eB[256 + tid];
    float2 fA[8], fB[8];
    {
        const uint32_t* a0 = reinterpret_cast<const uint32_t*>(&vA0);
        const uint32_t* a1 = reinterpret_cast<const uint32_t*>(&vA1);
        const uint32_t* b0 = reinterpret_cast<const uint32_t*>(&vB0);
        const uint32_t* b1 = reinterpret_cast<const uint32_t*>(&vB1);
#pragma unroll
        for (int q = 0; q < 4; ++q) {
            fA[q]     = __half22float2(*reinterpret_cast<const __half2*>(&a0[q]));
            fA[4 + q] = __half22float2(*reinterpret_cast<const __half2*>(&a1[q]));
            fB[q]     = __half22float2(*reinterpret_cast<const __half2*>(&b0[q]));
            fB[4 + q] = __half22float2(*reinterpret_cast<const __half2*>(&b1[q]));
        }
    }
    float lminA = 3.0e38f, lminB = 3.0e38f;
#pragma unroll
    for (int q = 0; q < 8; ++q) {
        lminA = fminf(lminA, fminf(fA[q].x, fA[q].y));
        lminB = fminf(lminB, fminf(fB[q].x, fB[q].y));
    }
#pragma unroll
    for (int off = 16; off > 0; off >>= 1) {
        lminA = fminf(lminA, __shfl_xor_sync(0xFFFFFFFFu, lminA, off));
        lminB = fminf(lminB, __shfl_xor_sync(0xFFFFFFFFu, lminB, off));
    }
    if (lid == 0) { red[0][wid] = lminA; red[1][wid] = lminB; }
    if (tid == 0) { ccount[0] = 0; ccount[1] = 0; }
    __syncthreads();
    float rowminA = red[0][0], rowminB = red[1][0];
#pragma unroll
    for (int w = 1; w < 8; ++w) {
        rowminA = fminf(rowminA, red[0][w]);
        rowminB = fminf(rowminB, red[1][w]);
    }

    const float thrA = rowminA + MARGIN;
    const float thrB = rowminB + MARGIN;
#pragma unroll
    for (int q = 0; q < 8; ++q) {
        const int j = (q < 4) ? (tid * 8 + q * 2) : (2048 + tid * 8 + (q - 4) * 2);
        if (fA[q].x <= thrA && j != rowA) {
            int p = atomicAdd(&ccount[0], 1);
            if (p < 64) cand[0][p] = j;
        }
        if (fA[q].y <= thrA && j + 1 != rowA) {
            int p = atomicAdd(&ccount[0], 1);
            if (p < 64) cand[0][p] = j + 1;
        }
        if (fB[q].x <= thrB && j != rowB) {
            int p = atomicAdd(&ccount[1], 1);
            if (p < 64) cand[1][p] = j;
        }
        if (fB[q].y <= thrB && j + 1 != rowB) {
            int p = atomicAdd(&ccount[1], 1);
            if (p < 64) cand[1][p] = j + 1;
        }
    }
    for (int j = tid; j < DDIM; j += 256) {
        arow[0][j] = out[(size_t)rowA * OLD + j];
        arow[1][j] = out[(size_t)rowB * OLD + j];
    }
    __syncthreads();

#pragma unroll
    for (int r = 0; r < 2; ++r) {
        const int row = rowA + r;
        int nc = ccount[r]; if (nc > 64) nc = 64;
        unsigned long long best = ~0ull;
        for (int k = 0; k < nc; ++k) {
            const int j = cand[r][k];
            const float* prow = &out[(size_t)j * OLD + DDIM];
            float s = 0.f;
            for (int tt = tid; tt < DDIM; tt += 256) s = fmaf(arow[r][tt], prow[tt], s);
#pragma unroll
            for (int off = 16; off > 0; off >>= 1)
                s += __shfl_xor_sync(0xFFFFFFFFu, s, off);
            if (lid == 0) red[0][wid] = s;
            __syncthreads();
            if (tid == 0) {
                float dot = 0.f;
#pragma unroll
                for (int w = 0; w < 8; ++w) dot += red[0][w];
                float dist = fmaf(-2.0f, dot, g_p2[j]);
                unsigned long long pk =
                    ((unsigned long long)__float_as_uint(dist) << 32) | (unsigned)j;
                if (pk < best) best = pk;
            }
            __syncthreads();
        }
        if (tid == 0) g_idx[row] = (int)(unsigned)(best & 0xFFFFFFFFull);
    }
}

// ---------------------------------------------------------------------------
// Gather hard negatives: out[:, 2048:3072] = pos[argmin]
// ---------------------------------------------------------------------------
__global__ __launch_bounds__(256) void gather_kernel(float* __restrict__ out) {
    const int row = blockIdx.x;
    const int idx = g_idx[row];
    const float4* src = reinterpret_cast<const float4*>(out + (size_t)idx * OLD + DDIM);
    float4* dst = reinterpret_cast<float4*>(out + (size_t)row * OLD + 2 * DDIM);
    dst[threadIdx.x] = src[threadIdx.x];
}

// ---------------------------------------------------------------------------
extern "C" void kernel_launch(void* const* d_in, const int* in_sizes, int n_in,
                              void* d_out, int out_size) {
    (void)in_sizes; (void)n_in; (void)out_size;
    const float* ax   = (const float*)d_in[0];
    const float* px   = (const float*)d_in[1];
    const float* W    = (const float*)d_in[2];
    const float* bias = (const float*)d_in[3];
    float* out = (float*)d_out;

    cudaFuncSetAttribute(proj_mma_kernel,
                         cudaFuncAttributeMaxDynamicSharedMemorySize, PSMEM_BYTES);
    cudaFuncSetAttribute(dist_est_kernel,
                         cudaFuncAttributeMaxDynamicSharedMemorySize, DSMEM_BYTES);

    void* p2addr = nullptr;
    cudaGetSymbolAddress(&p2addr, g_p2);
    cudaMemsetAsync(p2addr, 0, NB * sizeof(float));

    split_x_kernel<<<dim3(NB * DDIM / (256 * 16), 2), 256>>>(ax, px);
    split_w_kernel<<<dim3(DDIM / 32, DDIM / 32), 256>>>(W);
    proj_mma_kernel<<<PROJ_GRID, 256, PSMEM_BYTES>>>(bias, out);
    dist_est_kernel<<<DIST_GRID, 256, DSMEM_BYTES>>>();
    refine_kernel<<<NB / 2, 256>>>(out);
    gather_kernel<<<NB, 256>>>(out);
}

// round 16
// speedup vs baseline: 1.0814x; 1.0140x over previous
#include <cuda_runtime.h>
#include <cuda_bf16.h>
#include <cuda_fp16.h>
#include <cstdint>

#define NB   4096
#define DDIM 1024
#define OLD  3072

#define NSM       148
#define DIST_GRID (2 * NSM)   // 2 CTAs/SM, persistent
#define PROJ_GRID NSM         // 1 CTA/SM, persistent
#define DIST_NT   1024        // 32x32 tiles of 128x128
#define PROJ_NT   512         // 8(n) x 32(m) x 2(z) tiles

// ---------------- scratch globals (no allocs allowed) ----------------
__device__ __nv_bfloat16 g_xhi[2ull * NB * DDIM];   // input splits (anchor,pos)
__device__ __nv_bfloat16 g_xlo[2ull * NB * DDIM];
__device__ __nv_bfloat16 g_whi[DDIM * DDIM];        // W transposed [n][k], hi
__device__ __nv_bfloat16 g_wlo[DDIM * DDIM];        // W transposed [n][k], lo
__device__ __nv_bfloat16 g_abf[NB * DDIM];          // anchor output bf16
__device__ __nv_bfloat16 g_pbf[NB * DDIM];          // pos output bf16
__device__ float  g_p2[NB];                         // ||pos||^2 (atomic-accumulated)
__device__ __half g_est[(size_t)NB * NB];           // estimated dist (32MB)
__device__ int    g_idx[NB];                        // final argmin

__device__ __forceinline__ uint32_t smem_u32(const void* p) {
    uint32_t a;
    asm("{ .reg .u64 t; cvta.to.shared.u64 t, %1; cvt.u32.u64 %0, t; }" : "=r"(a) : "l"(p));
    return a;
}
#define SWZ(o) ((uint32_t)(o) ^ ((((uint32_t)(o)) >> 3) & 0x70u))

// ---------------------------------------------------------------------------
// Split inputs into bf16 hi/lo. 16 floats per thread, 4 upfront loads (MLP=4).
// ---------------------------------------------------------------------------
__global__ __launch_bounds__(256) void split_x_kernel(
    const float* __restrict__ ax, const float* __restrict__ px)
{
    const float* X = blockIdx.y ? px : ax;
    __nv_bfloat16* hi = g_xhi + (size_t)blockIdx.y * NB * DDIM;
    __nv_bfloat16* lo = g_xlo + (size_t)blockIdx.y * NB * DDIM;
    const size_t base = ((size_t)blockIdx.x * 256 + threadIdx.x) * 16;
    float4 v[4];
#pragma unroll
    for (int q = 0; q < 4; ++q)
        v[q] = *reinterpret_cast<const float4*>(X + base + q * 4);
#pragma unroll
    for (int q = 0; q < 2; ++q) {
        float f[8] = {v[q*2].x, v[q*2].y, v[q*2].z, v[q*2].w,
                      v[q*2+1].x, v[q*2+1].y, v[q*2+1].z, v[q*2+1].w};
        __align__(16) __nv_bfloat16 h[8], l[8];
#pragma unroll
        for (int i = 0; i < 8; ++i) {
            h[i] = __float2bfloat16(f[i]);
            l[i] = __float2bfloat16(f[i] - __bfloat162float(h[i]));
        }
        *reinterpret_cast<uint4*>(hi + base + q * 8) = *reinterpret_cast<uint4*>(h);
        *reinterpret_cast<uint4*>(lo + base + q * 8) = *reinterpret_cast<uint4*>(l);
    }
}

// ---------------------------------------------------------------------------
// Transpose + split W: g_whi/g_wlo[n][k] = split(W[k][n])
// ---------------------------------------------------------------------------
__global__ __launch_bounds__(256) void split_w_kernel(const float* __restrict__ W) {
    __shared__ float t[32][33];
    const int k0 = blockIdx.y * 32, n0 = blockIdx.x * 32;
    const int tx = threadIdx.x & 31, ty = threadIdx.x >> 5;  // 32x8
#pragma unroll
    for (int i = 0; i < 4; ++i)
        t[ty + i * 8][tx] = W[(size_t)(k0 + ty + i * 8) * DDIM + n0 + tx];
    __syncthreads();
#pragma unroll
    for (int i = 0; i < 4; ++i) {
        const int n = n0 + ty + i * 8;
        const float v = t[tx][ty + i * 8];
        __nv_bfloat16 h = __float2bfloat16(v);
        __nv_bfloat16 l = __float2bfloat16(v - __bfloat162float(h));
        g_whi[(size_t)n * DDIM + k0 + tx] = h;
        g_wlo[(size_t)n * DDIM + k0 + tx] = l;
    }
}

// ---------------------------------------------------------------------------
// Projection GEMM, bf16x3 HMMA, PERSISTENT CTAs: out = X@W + b
// 128x128 tile, BK=64, cp.async double-buffer flowing across tiles.
// Epilogue accumulates ||pos_row||^2 into g_p2 (z==1).
// ---------------------------------------------------------------------------
#define PT (128 * 128)               // 16KB: one tile (128 rows x 128B)
#define PSMEM_BYTES (8 * PT)         // 4 tiles x 2 stages = 128KB
#define NKC (DDIM / 64)              // 16

__device__ __forceinline__ void proj_tile_coords(int t, size_t& m_base, int& bn) {
    const int z = t >> 8;                  // 0..1
    const int bm = ((t >> 3) & 31) * 128;  // 0..3968
    bn = (t & 7) * 128;                    // 0..896
    m_base = (size_t)z * NB + bm;
}

__device__ __forceinline__ void proj_load_stage(uint32_t ss, size_t m_base,
                                                int bn, int kc, int tid) {
#pragma unroll
    for (int it = 0; it < 4; ++it) {
        int idx = it * 256 + tid;
        int r = idx >> 3, c = idx & 7;
        uint32_t so = SWZ(r * 128 + c * 16);
        const size_t ka = (m_base + r) * DDIM + kc * 64 + c * 8;
        const size_t kb = (size_t)(bn + r) * DDIM + kc * 64 + c * 8;
        asm volatile("cp.async.cg.shared.global [%0], [%1], 16;"
                     :: "r"(ss + so), "l"((const void*)&g_xhi[ka]));
        asm volatile("cp.async.cg.shared.global [%0], [%1], 16;"
                     :: "r"(ss + PT + so), "l"((const void*)&g_xlo[ka]));
        asm volatile("cp.async.cg.shared.global [%0], [%1], 16;"
                     :: "r"(ss + 2 * PT + so), "l"((const void*)&g_whi[kb]));
        asm volatile("cp.async.cg.shared.global [%0], [%1], 16;"
                     :: "r"(ss + 3 * PT + so), "l"((const void*)&g_wlo[kb]));
    }
    asm volatile("cp.async.commit_group;" ::: "memory");
}

__global__ __launch_bounds__(256, 1) void proj_mma_kernel(
    const float* __restrict__ bias, float* __restrict__ out)
{
    extern __shared__ __align__(1024) char smem[];
    const uint32_t sb = smem_u32(smem);
    const int tid = threadIdx.x;
    const int wid = tid >> 5, lane = tid & 31;
    const int m_off = (wid & 3) * 32;
    const int n_off = (wid >> 2) * 64;
    const int mi = lane >> 3;
    const int mr = lane & 7;
    const uint32_t stage[2] = {sb, sb + 4 * PT};
    const int stride = gridDim.x;

    int t = blockIdx.x;
    if (t < PROJ_NT) {
        size_t mb0; int bn0;
        proj_tile_coords(t, mb0, bn0);
        proj_load_stage(stage[0], mb0, bn0, 0, tid);
    }

    for (; t < PROJ_NT; t += stride) {
        size_t m_base; int bn;
        proj_tile_coords(t, m_base, bn);

        float acc[2][8][4];
#pragma unroll
        for (int i = 0; i < 2; ++i)
#pragma unroll
            for (int j = 0; j < 8; ++j)
#pragma unroll
                for (int c = 0; c < 4; ++c) acc[i][j][c] = 0.f;

        for (int kc = 0; kc < NKC; ++kc) {
            const int cur = kc & 1;
            bool have_next;
            if (kc + 1 < NKC) {
                proj_load_stage(stage[cur ^ 1], m_base, bn, kc + 1, tid);
                have_next = true;
            } else if (t + stride < PROJ_NT) {
                size_t mb2; int bn2;
                proj_tile_coords(t + stride, mb2, bn2);
                proj_load_stage(stage[cur ^ 1], mb2, bn2, 0, tid);
                have_next = true;
            } else {
                have_next = false;
            }
            if (have_next) asm volatile("cp.async.wait_group 1;" ::: "memory");
            else           asm volatile("cp.async.wait_group 0;" ::: "memory");
            __syncthreads();
            const uint32_t sAh = stage[cur], sAl = stage[cur] + PT;
            const uint32_t sBh = stage[cur] + 2 * PT, sBl = stage[cur] + 3 * PT;

#pragma unroll
            for (int ks = 0; ks < 4; ++ks) {
                const int arow0 = m_off + ((mi & 1) << 3) + mr;
                const int akb = ks * 32 + ((mi >> 1) << 4);
                uint32_t ah[2][4], al[2][4];
#pragma unroll
                for (int i = 0; i < 2; ++i) {
                    uint32_t off = SWZ((arow0 + i * 16) * 128 + akb);
                    asm volatile(
                        "ldmatrix.sync.aligned.m8n8.x4.shared.b16 {%0,%1,%2,%3}, [%4];"
                        : "=r"(ah[i][0]), "=r"(ah[i][1]), "=r"(ah[i][2]), "=r"(ah[i][3])
                        : "r"(sAh + off));
                    asm volatile(
                        "ldmatrix.sync.aligned.m8n8.x4.shared.b16 {%0,%1,%2,%3}, [%4];"
                        : "=r"(al[i][0]), "=r"(al[i][1]), "=r"(al[i][2]), "=r"(al[i][3])
                        : "r"(sAl + off));
                }
                uint32_t bh[4][4], bl[4][4];
                const int brow0 = n_off + ((mi >> 1) << 3) + mr;
                const int bkb = ks * 32 + ((mi & 1) << 4);
#pragma unroll
                for (int j2 = 0; j2 < 4; ++j2) {
                    uint32_t off = SWZ((brow0 + j2 * 16) * 128 + bkb);
                    asm volatile(
                        "ldmatrix.sync.aligned.m8n8.x4.shared.b16 {%0,%1,%2,%3}, [%4];"
                        : "=r"(bh[j2][0]), "=r"(bh[j2][1]), "=r"(bh[j2][2]), "=r"(bh[j2][3])
                        : "r"(sBh + off));
                    asm volatile(
                        "ldmatrix.sync.aligned.m8n8.x4.shared.b16 {%0,%1,%2,%3}, [%4];"
                        : "=r"(bl[j2][0]), "=r"(bl[j2][1]), "=r"(bl[j2][2]), "=r"(bl[j2][3])
                        : "r"(sBl + off));
                }
#pragma unroll
                for (int i = 0; i < 2; ++i)
#pragma unroll
                    for (int j = 0; j < 8; ++j) {
                        const int q = j >> 1, s = (j & 1) * 2;
#define PROJ_MMA(AF, B0, B1)                                                   \
    asm volatile(                                                              \
        "mma.sync.aligned.m16n8k16.row.col.f32.bf16.bf16.f32 "                 \
        "{%0,%1,%2,%3}, {%4,%5,%6,%7}, {%8,%9}, {%0,%1,%2,%3};"                \
        : "+f"(acc[i][j][0]), "+f"(acc[i][j][1]),                              \
          "+f"(acc[i][j][2]), "+f"(acc[i][j][3])                               \
        : "r"(AF[i][0]), "r"(AF[i][1]), "r"(AF[i][2]), "r"(AF[i][3]),          \
          "r"(B0), "r"(B1))
                        PROJ_MMA(ah, bh[q][s], bh[q][s + 1]);
                        PROJ_MMA(ah, bl[q][s], bl[q][s + 1]);
                        PROJ_MMA(al, bh[q][s], bh[q][s + 1]);
#undef PROJ_MMA
                    }
            }
            __syncthreads();
        }

        // epilogue (next tile's chunk-0 loads already in flight)
        const int z = t >> 8;
        const int bm = ((t >> 3) & 31) * 128;
        const int coloff = z ? DDIM : 0;
        __nv_bfloat16* bf = z ? g_pbf : g_abf;
        const int g = lane >> 2;
        const int c2 = (lane & 3) * 2;
#pragma unroll
        for (int i = 0; i < 2; ++i) {
            float s0 = 0.f, s1 = 0.f;
#pragma unroll
            for (int j = 0; j < 8; ++j) {
                const int ncol = bn + n_off + j * 8 + c2;
                const float b0 = bias[ncol], b1 = bias[ncol + 1];
                const int r0 = bm + m_off + i * 16 + g;
                const int r1 = r0 + 8;
                float v00 = acc[i][j][0] + b0, v01 = acc[i][j][1] + b1;
                float v10 = acc[i][j][2] + b0, v11 = acc[i][j][3] + b1;
                *reinterpret_cast<float2*>(&out[(size_t)r0 * OLD + coloff + ncol]) =
                    make_float2(v00, v01);
                *reinterpret_cast<float2*>(&out[(size_t)r1 * OLD + coloff + ncol]) =
                    make_float2(v10, v11);
                __nv_bfloat162 c0 = __floats2bfloat162_rn(v00, v01);
                __nv_bfloat162 c1 = __floats2bfloat162_rn(v10, v11);
                *reinterpret_cast<uint32_t*>(&bf[(size_t)r0 * DDIM + ncol]) =
                    *reinterpret_cast<uint32_t*>(&c0);
                *reinterpret_cast<uint32_t*>(&bf[(size_t)r1 * DDIM + ncol]) =
                    *reinterpret_cast<uint32_t*>(&c1);
                s0 = fmaf(v00, v00, fmaf(v01, v01, s0));
                s1 = fmaf(v10, v10, fmaf(v11, v11, s1));
            }
            if (z) {
                const int r0 = bm + m_off + i * 16 + g;
                atomicAdd(&g_p2[r0], s0);
                atomicAdd(&g_p2[r0 + 8], s1);
            }
        }
    }
}

// ---------------------------------------------------------------------------
// Phase 1: bf16 mma.sync dist estimate -> half est matrix, PERSISTENT CTAs.
// Strided tile walk (t += gridDim) — best-measured configuration (R12).
// ---------------------------------------------------------------------------
#define TILE_BYTES (128 * 128)
#define DSMEM_BYTES (4 * TILE_BYTES)

__device__ __forceinline__ void dist_load_stage(uint32_t sA, uint32_t sB,
                                                int bm, int bn, int kc, int tid) {
#pragma unroll
    for (int it = 0; it < 4; ++it) {
        int idx = it * 256 + tid;
        int r = idx >> 3, c = idx & 7;
        uint32_t so = SWZ(r * 128 + c * 16);
        asm volatile("cp.async.cg.shared.global [%0], [%1], 16;"
                     :: "r"(sA + so),
                        "l"((const void*)&g_abf[(size_t)(bm + r) * DDIM + kc * 64 + c * 8]));
        asm volatile("cp.async.cg.shared.global [%0], [%1], 16;"
                     :: "r"(sB + so),
                        "l"((const void*)&g_pbf[(size_t)(bn + r) * DDIM + kc * 64 + c * 8]));
    }
    asm volatile("cp.async.commit_group;" ::: "memory");
}

__global__ __launch_bounds__(256, 2) void dist_est_kernel() {
    extern __shared__ __align__(1024) char smem[];
    const uint32_t sb = smem_u32(smem);
    const int tid = threadIdx.x;
    const int wid = tid >> 5, lane = tid & 31;
    const int m_off = (wid & 3) * 32;
    const int n_off = (wid >> 2) * 64;
    const int mi = lane >> 3;
    const int mr = lane & 7;
    const uint32_t sA[2] = {sb,              sb + 2 * TILE_BYTES};
    const uint32_t sB[2] = {sb + TILE_BYTES, sb + 3 * TILE_BYTES};
    const int stride = gridDim.x;

    int t = blockIdx.x;
    if (t < DIST_NT)
        dist_load_stage(sA[0], sB[0], (t >> 5) * 128, (t & 31) * 128, 0, tid);

    for (; t < DIST_NT; t += stride) {
        const int bm = (t >> 5) * 128;
        const int bn = (t & 31) * 128;

        float acc[2][8][4];
#pragma unroll
        for (int i = 0; i < 2; ++i)
#pragma unroll
            for (int j = 0; j < 8; ++j)
#pragma unroll
                for (int c = 0; c < 4; ++c) acc[i][j][c] = 0.f;

        for (int kc = 0; kc < NKC; ++kc) {
            const int cur = kc & 1;
            bool have_next;
            if (kc + 1 < NKC) {
                dist_load_stage(sA[cur ^ 1], sB[cur ^ 1], bm, bn, kc + 1, tid);
                have_next = true;
            } else if (t + stride < DIST_NT) {
                const int t2 = t + stride;
                dist_load_stage(sA[cur ^ 1], sB[cur ^ 1],
                                (t2 >> 5) * 128, (t2 & 31) * 128, 0, tid);
                have_next = true;
            } else {
                have_next = false;
            }
            if (have_next) asm volatile("cp.async.wait_group 1;" ::: "memory");
            else           asm volatile("cp.async.wait_group 0;" ::: "memory");
            __syncthreads();

#pragma unroll
            for (int ks = 0; ks < 4; ++ks) {
                uint32_t a[2][4];
#pragma unroll
                for (int i = 0; i < 2; ++i) {
                    int row = m_off + i * 16 + ((mi & 1) << 3) + mr;
                    int kb = ks * 32 + ((mi >> 1) << 4);
                    asm volatile(
                        "ldmatrix.sync.aligned.m8n8.x4.shared.b16 {%0,%1,%2,%3}, [%4];"
                        : "=r"(a[i][0]), "=r"(a[i][1]), "=r"(a[i][2]), "=r"(a[i][3])
                        : "r"(sA[cur] + SWZ(row * 128 + kb)));
                }
                uint32_t b[4][4];
#pragma unroll
                for (int j2 = 0; j2 < 4; ++j2) {
                    int row = n_off + j2 * 16 + ((mi >> 1) << 3) + mr;
                    int kb = ks * 32 + ((mi & 1) << 4);
                    asm volatile(
                        "ldmatrix.sync.aligned.m8n8.x4.shared.b16 {%0,%1,%2,%3}, [%4];"
                        : "=r"(b[j2][0]), "=r"(b[j2][1]), "=r"(b[j2][2]), "=r"(b[j2][3])
                        : "r"(sB[cur] + SWZ(row * 128 + kb)));
                }
#pragma unroll
                for (int i = 0; i < 2; ++i)
#pragma unroll
                    for (int j = 0; j < 8; ++j) {
                        const uint32_t b0 = b[j >> 1][(j & 1) * 2];
                        const uint32_t b1 = b[j >> 1][(j & 1) * 2 + 1];
                        asm volatile(
                            "mma.sync.aligned.m16n8k16.row.col.f32.bf16.bf16.f32 "
                            "{%0,%1,%2,%3}, {%4,%5,%6,%7}, {%8,%9}, {%0,%1,%2,%3};"
                            : "+f"(acc[i][j][0]), "+f"(acc[i][j][1]),
                              "+f"(acc[i][j][2]), "+f"(acc[i][j][3])
                            : "r"(a[i][0]), "r"(a[i][1]), "r"(a[i][2]), "r"(a[i][3]),
                              "r"(b0), "r"(b1));
                    }
            }
            __syncthreads();
        }

        // epilogue (next tile's chunk-0 loads already in flight)
        const int g = lane >> 2;
        const int c2 = (lane & 3) * 2;
#pragma unroll
        for (int i = 0; i < 2; ++i) {
#pragma unroll
            for (int j = 0; j < 8; ++j) {
                const int ncol = bn + n_off + j * 8 + c2;
                const float p2a = g_p2[ncol];
                const float p2b = g_p2[ncol + 1];
                const int r0 = bm + m_off + i * 16 + g;
                const int r1 = r0 + 8;
                float e00 = fmaf(-2.f, acc[i][j][0], p2a);
                float e01 = fmaf(-2.f, acc[i][j][1], p2b);
                float e10 = fmaf(-2.f, acc[i][j][2], p2a);
                float e11 = fmaf(-2.f, acc[i][j][3], p2b);
                if (ncol == r0) e00 = 65504.f;
                if (ncol + 1 == r0) e01 = 65504.f;
                if (ncol == r1) e10 = 65504.f;
                if (ncol + 1 == r1) e11 = 65504.f;
                *reinterpret_cast<__half2*>(&g_est[(size_t)r0 * NB + ncol]) =
                    __floats2half2_rn(e00, e01);
                *reinterpret_cast<__half2*>(&g_est[(size_t)r1 * NB + ncol]) =
                    __floats2half2_rn(e10, e11);
            }
        }
    }
}

// ---------------------------------------------------------------------------
// Phase 2: per-row refine — 2 rows per block, exact fp32 distance on
// candidates within MARGIN. Deterministic.
// ---------------------------------------------------------------------------
#define MARGIN 6.0f

__global__ __launch_bounds__(256) void refine_kernel(const float* __restrict__ out) {
    const int rowA = blockIdx.x * 2;
    const int rowB = rowA + 1;
    const int tid = threadIdx.x;
    const int wid = tid >> 5, lid = tid & 31;
    const uint4* eA = reinterpret_cast<const uint4*>(&g_est[(size_t)rowA * NB]);
    const uint4* eB = reinterpret_cast<const uint4*>(&g_est[(size_t)rowB * NB]);

    __shared__ float red[2][8];
    __shared__ int   cand[2][64];
    __shared__ int   ccount[2];
    __shared__ float arow[2][DDIM];

    uint4 vA0 = eA[tid];
    uint4 vA1 = eA[256 + tid];
    uint4 vB0 = eB[tid];
    uint4 vB1 = eB[256 + tid];
    float2 fA[8], fB[8];
    {
        const uint32_t* a0 = reinterpret_cast<const uint32_t*>(&vA0);
        const uint32_t* a1 = reinterpret_cast<const uint32_t*>(&vA1);
        const uint32_t* b0 = reinterpret_cast<const uint32_t*>(&vB0);
        const uint32_t* b1 = reinterpret_cast<const uint32_t*>(&vB1);
#pragma unroll
        for (int q = 0; q < 4; ++q) {
            fA[q]     = __half22float2(*reinterpret_cast<const __half2*>(&a0[q]));
            fA[4 + q] = __half22float2(*reinterpret_cast<const __half2*>(&a1[q]));
            fB[q]     = __half22float2(*reinterpret_cast<const __half2*>(&b0[q]));
            fB[4 + q] = __half22float2(*reinterpret_cast<const __half2*>(&b1[q]));
        }
    }
    float lminA = 3.0e38f, lminB = 3.0e38f;
#pragma unroll
    for (int q = 0; q < 8; ++q) {
        lminA = fminf(lminA, fminf(fA[q].x, fA[q].y));
        lminB = fminf(lminB, fminf(fB[q].x, fB[q].y));
    }
#pragma unroll
    for (int off = 16; off > 0; off >>= 1) {
        lminA = fminf(lminA, __shfl_xor_sync(0xFFFFFFFFu, lminA, off));
        lminB = fminf(lminB, __shfl_xor_sync(0xFFFFFFFFu, lminB, off));
    }
    if (lid == 0) { red[0][wid] = lminA; red[1][wid] = lminB; }
    if (tid == 0) { ccount[0] = 0; ccount[1] = 0; }
    __syncthreads();
    float rowminA = red[0][0], rowminB = red[1][0];
#pragma unroll
    for (int w = 1; w < 8; ++w) {
        rowminA = fminf(rowminA, red[0][w]);
        rowminB = fminf(rowminB, red[1][w]);
    }

    const float thrA = rowminA + MARGIN;
    const float thrB = rowminB + MARGIN;
#pragma unroll
    for (int q = 0; q < 8; ++q) {
        const int j = (q < 4) ? (tid * 8 + q * 2) : (2048 + tid * 8 + (q - 4) * 2);
        if (fA[q].x <= thrA && j != rowA) {
            int p = atomicAdd(&ccount[0], 1);
            if (p < 64) cand[0][p] = j;
        }
        if (fA[q].y <= thrA && j + 1 != rowA) {
            int p = atomicAdd(&ccount[0], 1);
            if (p < 64) cand[0][p] = j + 1;
        }
        if (fB[q].x <= thrB && j != rowB) {
            int p = atomicAdd(&ccount[1], 1);
            if (p < 64) cand[1][p] = j;
        }
        if (fB[q].y <= thrB && j + 1 != rowB) {
            int p = atomicAdd(&ccount[1], 1);
            if (p < 64) cand[1][p] = j + 1;
        }
    }
    for (int j = tid; j < DDIM; j += 256) {
        arow[0][j] = out[(size_t)rowA * OLD + j];
        arow[1][j] = out[(size_t)rowB * OLD + j];
    }
    __syncthreads();

#pragma unroll
    for (int r = 0; r < 2; ++r) {
        const int row = rowA + r;
        int nc = ccount[r]; if (nc > 64) nc = 64;
        unsigned long long best = ~0ull;
        for (int k = 0; k < nc; ++k) {
            const int j = cand[r][k];
            const float* prow = &out[(size_t)j * OLD + DDIM];
            float s = 0.f;
            for (int tt = tid; tt < DDIM; tt += 256) s = fmaf(arow[r][tt], prow[tt], s);
#pragma unroll
            for (int off = 16; off > 0; off >>= 1)
                s += __shfl_xor_sync(0xFFFFFFFFu, s, off);
            if (lid == 0) red[0][wid] = s;
            __syncthreads();
            if (tid == 0) {
                float dot = 0.f;
#pragma unroll
                for (int w = 0; w < 8; ++w) dot += red[0][w];
                float dist = fmaf(-2.0f, dot, g_p2[j]);
                unsigned long long pk =
                    ((unsigned long long)__float_as_uint(dist) << 32) | (unsigned)j;
                if (pk < best) best = pk;
            }
            __syncthreads();
        }
        if (tid == 0) g_idx[row] = (int)(unsigned)(best & 0xFFFFFFFFull);
    }
}

// ---------------------------------------------------------------------------
// Gather hard negatives: out[:, 2048:3072] = pos[argmin]
// ---------------------------------------------------------------------------
__global__ __launch_bounds__(256) void gather_kernel(float* __restrict__ out) {
    const int row = blockIdx.x;
    const int idx = g_idx[row];
    const float4* src = reinterpret_cast<const float4*>(out + (size_t)idx * OLD + DDIM);
    float4* dst = reinterpret_cast<float4*>(out + (size_t)row * OLD + 2 * DDIM);
    dst[threadIdx.x] = src[threadIdx.x];
}

// ---------------------------------------------------------------------------
extern "C" void kernel_launch(void* const* d_in, const int* in_sizes, int n_in,
                              void* d_out, int out_size) {
    (void)in_sizes; (void)n_in; (void)out_size;
    const float* ax   = (const float*)d_in[0];
    const float* px   = (const float*)d_in[1];
    const float* W    = (const float*)d_in[2];
    const float* bias = (const float*)d_in[3];
    float* out = (float*)d_out;

    cudaFuncSetAttribute(proj_mma_kernel,
                         cudaFuncAttributeMaxDynamicSharedMemorySize, PSMEM_BYTES);
    cudaFuncSetAttribute(dist_est_kernel,
                         cudaFuncAttributeMaxDynamicSharedMemorySize, DSMEM_BYTES);

    void* p2addr = nullptr;
    cudaGetSymbolAddress(&p2addr, g_p2);
    cudaMemsetAsync(p2addr, 0, NB * sizeof(float));

    split_x_kernel<<<dim3(NB * DDIM / (256 * 16), 2), 256>>>(ax, px);
    split_w_kernel<<<dim3(DDIM / 32, DDIM / 32), 256>>>(W);
    proj_mma_kernel<<<PROJ_GRID, 256, PSMEM_BYTES>>>(bias, out);
    dist_est_kernel<<<DIST_GRID, 256, DSMEM_BYTES>>>();
    refine_kernel<<<NB / 2, 256>>>(out);
    gather_kernel<<<NB, 256>>>(out);
}

// round 17
// speedup vs baseline: 1.0845x; 1.0029x over previous
#include <cuda_runtime.h>
#include <cuda_bf16.h>
#include <cuda_fp16.h>
#include <cstdint>

#define NB   4096
#define DDIM 1024
#define OLD  3072

#define NSM       148
#define DIST_GRID (2 * NSM)   // 2 CTAs/SM, persistent
#define PROJ_GRID NSM         // 1 CTA/SM, persistent
#define DIST_NT   1024        // 32x32 tiles of 128x128
#define PROJ_NT   512         // 8(n) x 32(m) x 2(z) tiles

// ---------------- scratch globals (no allocs allowed) ----------------
__device__ __nv_bfloat16 g_xhi[2ull * NB * DDIM];   // input splits (anchor,pos)
__device__ __nv_bfloat16 g_xlo[2ull * NB * DDIM];
__device__ __nv_bfloat16 g_whi[DDIM * DDIM];        // W transposed [n][k], hi
__device__ __nv_bfloat16 g_wlo[DDIM * DDIM];        // W transposed [n][k], lo
__device__ __nv_bfloat16 g_abf[NB * DDIM];          // anchor output bf16
__device__ __nv_bfloat16 g_pbf[NB * DDIM];          // pos output bf16
__device__ float  g_p2[NB];                         // ||pos||^2 (atomic-accumulated)
__device__ __half g_est[(size_t)NB * NB];           // estimated dist (32MB)
__device__ int    g_idx[NB];                        // final argmin

__device__ __forceinline__ uint32_t smem_u32(const void* p) {
    uint32_t a;
    asm("{ .reg .u64 t; cvta.to.shared.u64 t, %1; cvt.u32.u64 %0, t; }" : "=r"(a) : "l"(p));
    return a;
}
#define SWZ(o) ((uint32_t)(o) ^ ((((uint32_t)(o)) >> 3) & 0x70u))

// ---------------------------------------------------------------------------
// Split inputs into bf16 hi/lo. 16 floats per thread, 4 upfront loads (MLP=4).
// ---------------------------------------------------------------------------
__global__ __launch_bounds__(256) void split_x_kernel(
    const float* __restrict__ ax, const float* __restrict__ px)
{
    const float* X = blockIdx.y ? px : ax;
    __nv_bfloat16* hi = g_xhi + (size_t)blockIdx.y * NB * DDIM;
    __nv_bfloat16* lo = g_xlo + (size_t)blockIdx.y * NB * DDIM;
    const size_t base = ((size_t)blockIdx.x * 256 + threadIdx.x) * 16;
    float4 v[4];
#pragma unroll
    for (int q = 0; q < 4; ++q)
        v[q] = *reinterpret_cast<const float4*>(X + base + q * 4);
#pragma unroll
    for (int q = 0; q < 2; ++q) {
        float f[8] = {v[q*2].x, v[q*2].y, v[q*2].z, v[q*2].w,
                      v[q*2+1].x, v[q*2+1].y, v[q*2+1].z, v[q*2+1].w};
        __align__(16) __nv_bfloat16 h[8], l[8];
#pragma unroll
        for (int i = 0; i < 8; ++i) {
            h[i] = __float2bfloat16(f[i]);
            l[i] = __float2bfloat16(f[i] - __bfloat162float(h[i]));
        }
        *reinterpret_cast<uint4*>(hi + base + q * 8) = *reinterpret_cast<uint4*>(h);
        *reinterpret_cast<uint4*>(lo + base + q * 8) = *reinterpret_cast<uint4*>(l);
    }
}

// ---------------------------------------------------------------------------
// Transpose + split W: g_whi/g_wlo[n][k] = split(W[k][n])
// ---------------------------------------------------------------------------
__global__ __launch_bounds__(256) void split_w_kernel(const float* __restrict__ W) {
    __shared__ float t[32][33];
    const int k0 = blockIdx.y * 32, n0 = blockIdx.x * 32;
    const int tx = threadIdx.x & 31, ty = threadIdx.x >> 5;  // 32x8
#pragma unroll
    for (int i = 0; i < 4; ++i)
        t[ty + i * 8][tx] = W[(size_t)(k0 + ty + i * 8) * DDIM + n0 + tx];
    __syncthreads();
#pragma unroll
    for (int i = 0; i < 4; ++i) {
        const int n = n0 + ty + i * 8;
        const float v = t[tx][ty + i * 8];
        __nv_bfloat16 h = __float2bfloat16(v);
        __nv_bfloat16 l = __float2bfloat16(v - __bfloat162float(h));
        g_whi[(size_t)n * DDIM + k0 + tx] = h;
        g_wlo[(size_t)n * DDIM + k0 + tx] = l;
    }
}

// ---------------------------------------------------------------------------
// Projection GEMM, bf16x3 HMMA, PERSISTENT CTAs: out = X@W + b
// 128x128 tile, BK=64, cp.async double-buffer flowing across tiles.
// Epilogue accumulates ||pos_row||^2 into g_p2 (z==1).
// ---------------------------------------------------------------------------
#define PT (128 * 128)               // 16KB: one tile (128 rows x 128B)
#define PSMEM_BYTES (8 * PT)         // 4 tiles x 2 stages = 128KB
#define NKC (DDIM / 64)              // 16

__device__ __forceinline__ void proj_tile_coords(int t, size_t& m_base, int& bn) {
    const int z = t >> 8;                  // 0..1
    const int bm = ((t >> 3) & 31) * 128;  // 0..3968
    bn = (t & 7) * 128;                    // 0..896
    m_base = (size_t)z * NB + bm;
}

__device__ __forceinline__ void proj_load_stage(uint32_t ss, size_t m_base,
                                                int bn, int kc, int tid) {
#pragma unroll
    for (int it = 0; it < 4; ++it) {
        int idx = it * 256 + tid;
        int r = idx >> 3, c = idx & 7;
        uint32_t so = SWZ(r * 128 + c * 16);
        const size_t ka = (m_base + r) * DDIM + kc * 64 + c * 8;
        const size_t kb = (size_t)(bn + r) * DDIM + kc * 64 + c * 8;
        asm volatile("cp.async.cg.shared.global [%0], [%1], 16;"
                     :: "r"(ss + so), "l"((const void*)&g_xhi[ka]));
        asm volatile("cp.async.cg.shared.global [%0], [%1], 16;"
                     :: "r"(ss + PT + so), "l"((const void*)&g_xlo[ka]));
        asm volatile("cp.async.cg.shared.global [%0], [%1], 16;"
                     :: "r"(ss + 2 * PT + so), "l"((const void*)&g_whi[kb]));
        asm volatile("cp.async.cg.shared.global [%0], [%1], 16;"
                     :: "r"(ss + 3 * PT + so), "l"((const void*)&g_wlo[kb]));
    }
    asm volatile("cp.async.commit_group;" ::: "memory");
}

__global__ __launch_bounds__(256, 1) void proj_mma_kernel(
    const float* __restrict__ bias, float* __restrict__ out)
{
    extern __shared__ __align__(1024) char smem[];
    const uint32_t sb = smem_u32(smem);
    const int tid = threadIdx.x;
    const int wid = tid >> 5, lane = tid & 31;
    const int m_off = (wid & 3) * 32;
    const int n_off = (wid >> 2) * 64;
    const int mi = lane >> 3;
    const int mr = lane & 7;
    const uint32_t stage[2] = {sb, sb + 4 * PT};
    const int stride = gridDim.x;

    int t = blockIdx.x;
    if (t < PROJ_NT) {
        size_t mb0; int bn0;
        proj_tile_coords(t, mb0, bn0);
        proj_load_stage(stage[0], mb0, bn0, 0, tid);
    }

    for (; t < PROJ_NT; t += stride) {
        size_t m_base; int bn;
        proj_tile_coords(t, m_base, bn);

        float acc[2][8][4];
#pragma unroll
        for (int i = 0; i < 2; ++i)
#pragma unroll
            for (int j = 0; j < 8; ++j)
#pragma unroll
                for (int c = 0; c < 4; ++c) acc[i][j][c] = 0.f;

        for (int kc = 0; kc < NKC; ++kc) {
            const int cur = kc & 1;
            bool have_next;
            if (kc + 1 < NKC) {
                proj_load_stage(stage[cur ^ 1], m_base, bn, kc + 1, tid);
                have_next = true;
            } else if (t + stride < PROJ_NT) {
                size_t mb2; int bn2;
                proj_tile_coords(t + stride, mb2, bn2);
                proj_load_stage(stage[cur ^ 1], mb2, bn2, 0, tid);
                have_next = true;
            } else {
                have_next = false;
            }
            if (have_next) asm volatile("cp.async.wait_group 1;" ::: "memory");
            else           asm volatile("cp.async.wait_group 0;" ::: "memory");
            __syncthreads();
            const uint32_t sAh = stage[cur], sAl = stage[cur] + PT;
            const uint32_t sBh = stage[cur] + 2 * PT, sBl = stage[cur] + 3 * PT;

#pragma unroll
            for (int ks = 0; ks < 4; ++ks) {
                const int arow0 = m_off + ((mi & 1) << 3) + mr;
                const int akb = ks * 32 + ((mi >> 1) << 4);
                uint32_t ah[2][4], al[2][4];
#pragma unroll
                for (int i = 0; i < 2; ++i) {
                    uint32_t off = SWZ((arow0 + i * 16) * 128 + akb);
                    asm volatile(
                        "ldmatrix.sync.aligned.m8n8.x4.shared.b16 {%0,%1,%2,%3}, [%4];"
                        : "=r"(ah[i][0]), "=r"(ah[i][1]), "=r"(ah[i][2]), "=r"(ah[i][3])
                        : "r"(sAh + off));
                    asm volatile(
                        "ldmatrix.sync.aligned.m8n8.x4.shared.b16 {%0,%1,%2,%3}, [%4];"
                        : "=r"(al[i][0]), "=r"(al[i][1]), "=r"(al[i][2]), "=r"(al[i][3])
                        : "r"(sAl + off));
                }
                uint32_t bh[4][4], bl[4][4];
                const int brow0 = n_off + ((mi >> 1) << 3) + mr;
                const int bkb = ks * 32 + ((mi & 1) << 4);
#pragma unroll
                for (int j2 = 0; j2 < 4; ++j2) {
                    uint32_t off = SWZ((brow0 + j2 * 16) * 128 + bkb);
                    asm volatile(
                        "ldmatrix.sync.aligned.m8n8.x4.shared.b16 {%0,%1,%2,%3}, [%4];"
                        : "=r"(bh[j2][0]), "=r"(bh[j2][1]), "=r"(bh[j2][2]), "=r"(bh[j2][3])
                        : "r"(sBh + off));
                    asm volatile(
                        "ldmatrix.sync.aligned.m8n8.x4.shared.b16 {%0,%1,%2,%3}, [%4];"
                        : "=r"(bl[j2][0]), "=r"(bl[j2][1]), "=r"(bl[j2][2]), "=r"(bl[j2][3])
                        : "r"(sBl + off));
                }
#pragma unroll
                for (int i = 0; i < 2; ++i)
#pragma unroll
                    for (int j = 0; j < 8; ++j) {
                        const int q = j >> 1, s = (j & 1) * 2;
#define PROJ_MMA(AF, B0, B1)                                                   \
    asm volatile(                                                              \
        "mma.sync.aligned.m16n8k16.row.col.f32.bf16.bf16.f32 "                 \
        "{%0,%1,%2,%3}, {%4,%5,%6,%7}, {%8,%9}, {%0,%1,%2,%3};"                \
        : "+f"(acc[i][j][0]), "+f"(acc[i][j][1]),                              \
          "+f"(acc[i][j][2]), "+f"(acc[i][j][3])                               \
        : "r"(AF[i][0]), "r"(AF[i][1]), "r"(AF[i][2]), "r"(AF[i][3]),          \
          "r"(B0), "r"(B1))
                        PROJ_MMA(ah, bh[q][s], bh[q][s + 1]);
                        PROJ_MMA(ah, bl[q][s], bl[q][s + 1]);
                        PROJ_MMA(al, bh[q][s], bh[q][s + 1]);
#undef PROJ_MMA
                    }
            }
            __syncthreads();
        }

        // epilogue (next tile's chunk-0 loads already in flight)
        const int z = t >> 8;
        const int bm = ((t >> 3) & 31) * 128;
        const int coloff = z ? DDIM : 0;
        __nv_bfloat16* bf = z ? g_pbf : g_abf;
        const int g = lane >> 2;
        const int c2 = (lane & 3) * 2;
#pragma unroll
        for (int i = 0; i < 2; ++i) {
            float s0 = 0.f, s1 = 0.f;
#pragma unroll
            for (int j = 0; j < 8; ++j) {
                const int ncol = bn + n_off + j * 8 + c2;
                const float b0 = bias[ncol], b1 = bias[ncol + 1];
                const int r0 = bm + m_off + i * 16 + g;
                const int r1 = r0 + 8;
                float v00 = acc[i][j][0] + b0, v01 = acc[i][j][1] + b1;
                float v10 = acc[i][j][2] + b0, v11 = acc[i][j][3] + b1;
                *reinterpret_cast<float2*>(&out[(size_t)r0 * OLD + coloff + ncol]) =
                    make_float2(v00, v01);
                *reinterpret_cast<float2*>(&out[(size_t)r1 * OLD + coloff + ncol]) =
                    make_float2(v10, v11);
                __nv_bfloat162 c0 = __floats2bfloat162_rn(v00, v01);
                __nv_bfloat162 c1 = __floats2bfloat162_rn(v10, v11);
                *reinterpret_cast<uint32_t*>(&bf[(size_t)r0 * DDIM + ncol]) =
                    *reinterpret_cast<uint32_t*>(&c0);
                *reinterpret_cast<uint32_t*>(&bf[(size_t)r1 * DDIM + ncol]) =
                    *reinterpret_cast<uint32_t*>(&c1);
                s0 = fmaf(v00, v00, fmaf(v01, v01, s0));
                s1 = fmaf(v10, v10, fmaf(v11, v11, s1));
            }
            if (z) {
                const int r0 = bm + m_off + i * 16 + g;
                atomicAdd(&g_p2[r0], s0);
                atomicAdd(&g_p2[r0 + 8], s1);
            }
        }
    }
}

// ---------------------------------------------------------------------------
// Phase 1: bf16 mma.sync dist estimate -> half est matrix, PERSISTENT CTAs.
// Strided tile walk (t += gridDim) — best-measured configuration.
// ---------------------------------------------------------------------------
#define TILE_BYTES (128 * 128)
#define DSMEM_BYTES (4 * TILE_BYTES)

__device__ __forceinline__ void dist_load_stage(uint32_t sA, uint32_t sB,
                                                int bm, int bn, int kc, int tid) {
#pragma unroll
    for (int it = 0; it < 4; ++it) {
        int idx = it * 256 + tid;
        int r = idx >> 3, c = idx & 7;
        uint32_t so = SWZ(r * 128 + c * 16);
        asm volatile("cp.async.cg.shared.global [%0], [%1], 16;"
                     :: "r"(sA + so),
                        "l"((const void*)&g_abf[(size_t)(bm + r) * DDIM + kc * 64 + c * 8]));
        asm volatile("cp.async.cg.shared.global [%0], [%1], 16;"
                     :: "r"(sB + so),
                        "l"((const void*)&g_pbf[(size_t)(bn + r) * DDIM + kc * 64 + c * 8]));
    }
    asm volatile("cp.async.commit_group;" ::: "memory");
}

__global__ __launch_bounds__(256, 2) void dist_est_kernel() {
    extern __shared__ __align__(1024) char smem[];
    const uint32_t sb = smem_u32(smem);
    const int tid = threadIdx.x;
    const int wid = tid >> 5, lane = tid & 31;
    const int m_off = (wid & 3) * 32;
    const int n_off = (wid >> 2) * 64;
    const int mi = lane >> 3;
    const int mr = lane & 7;
    const uint32_t sA[2] = {sb,              sb + 2 * TILE_BYTES};
    const uint32_t sB[2] = {sb + TILE_BYTES, sb + 3 * TILE_BYTES};
    const int stride = gridDim.x;

    int t = blockIdx.x;
    if (t < DIST_NT)
        dist_load_stage(sA[0], sB[0], (t >> 5) * 128, (t & 31) * 128, 0, tid);

    for (; t < DIST_NT; t += stride) {
        const int bm = (t >> 5) * 128;
        const int bn = (t & 31) * 128;

        float acc[2][8][4];
#pragma unroll
        for (int i = 0; i < 2; ++i)
#pragma unroll
            for (int j = 0; j < 8; ++j)
#pragma unroll
                for (int c = 0; c < 4; ++c) acc[i][j][c] = 0.f;

        for (int kc = 0; kc < NKC; ++kc) {
            const int cur = kc & 1;
            bool have_next;
            if (kc + 1 < NKC) {
                dist_load_stage(sA[cur ^ 1], sB[cur ^ 1], bm, bn, kc + 1, tid);
                have_next = true;
            } else if (t + stride < DIST_NT) {
                const int t2 = t + stride;
                dist_load_stage(sA[cur ^ 1], sB[cur ^ 1],
                                (t2 >> 5) * 128, (t2 & 31) * 128, 0, tid);
                have_next = true;
            } else {
                have_next = false;
            }
            if (have_next) asm volatile("cp.async.wait_group 1;" ::: "memory");
            else           asm volatile("cp.async.wait_group 0;" ::: "memory");
            __syncthreads();

#pragma unroll
            for (int ks = 0; ks < 4; ++ks) {
                uint32_t a[2][4];
#pragma unroll
                for (int i = 0; i < 2; ++i) {
                    int row = m_off + i * 16 + ((mi & 1) << 3) + mr;
                    int kb = ks * 32 + ((mi >> 1) << 4);
                    asm volatile(
                        "ldmatrix.sync.aligned.m8n8.x4.shared.b16 {%0,%1,%2,%3}, [%4];"
                        : "=r"(a[i][0]), "=r"(a[i][1]), "=r"(a[i][2]), "=r"(a[i][3])
                        : "r"(sA[cur] + SWZ(row * 128 + kb)));
                }
                uint32_t b[4][4];
#pragma unroll
                for (int j2 = 0; j2 < 4; ++j2) {
                    int row = n_off + j2 * 16 + ((mi >> 1) << 3) + mr;
                    int kb = ks * 32 + ((mi & 1) << 4);
                    asm volatile(
                        "ldmatrix.sync.aligned.m8n8.x4.shared.b16 {%0,%1,%2,%3}, [%4];"
                        : "=r"(b[j2][0]), "=r"(b[j2][1]), "=r"(b[j2][2]), "=r"(b[j2][3])
                        : "r"(sB[cur] + SWZ(row * 128 + kb)));
                }
#pragma unroll
                for (int i = 0; i < 2; ++i)
#pragma unroll
                    for (int j = 0; j < 8; ++j) {
                        const uint32_t b0 = b[j >> 1][(j & 1) * 2];
                        const uint32_t b1 = b[j >> 1][(j & 1) * 2 + 1];
                        asm volatile(
                            "mma.sync.aligned.m16n8k16.row.col.f32.bf16.bf16.f32 "
                            "{%0,%1,%2,%3}, {%4,%5,%6,%7}, {%8,%9}, {%0,%1,%2,%3};"
                            : "+f"(acc[i][j][0]), "+f"(acc[i][j][1]),
                              "+f"(acc[i][j][2]), "+f"(acc[i][j][3])
                            : "r"(a[i][0]), "r"(a[i][1]), "r"(a[i][2]), "r"(a[i][3]),
                              "r"(b0), "r"(b1));
                    }
            }
            __syncthreads();
        }

        // epilogue (next tile's chunk-0 loads already in flight)
        const int g = lane >> 2;
        const int c2 = (lane & 3) * 2;
#pragma unroll
        for (int i = 0; i < 2; ++i) {
#pragma unroll
            for (int j = 0; j < 8; ++j) {
                const int ncol = bn + n_off + j * 8 + c2;
                const float p2a = g_p2[ncol];
                const float p2b = g_p2[ncol + 1];
                const int r0 = bm + m_off + i * 16 + g;
                const int r1 = r0 + 8;
                float e00 = fmaf(-2.f, acc[i][j][0], p2a);
                float e01 = fmaf(-2.f, acc[i][j][1], p2b);
                float e10 = fmaf(-2.f, acc[i][j][2], p2a);
                float e11 = fmaf(-2.f, acc[i][j][3], p2b);
                if (ncol == r0) e00 = 65504.f;
                if (ncol + 1 == r0) e01 = 65504.f;
                if (ncol == r1) e10 = 65504.f;
                if (ncol + 1 == r1) e11 = 65504.f;
                *reinterpret_cast<__half2*>(&g_est[(size_t)r0 * NB + ncol]) =
                    __floats2half2_rn(e00, e01);
                *reinterpret_cast<__half2*>(&g_est[(size_t)r1 * NB + ncol]) =
                    __floats2half2_rn(e10, e11);
            }
        }
    }
}

// ---------------------------------------------------------------------------
// Phase 2: per-row refine — 2 rows per block, exact fp32 distance on
// candidates within MARGIN. Deterministic.
// ---------------------------------------------------------------------------
#define MARGIN 6.0f

__global__ __launch_bounds__(256) void refine_kernel(const float* __restrict__ out) {
    const int rowA = blockIdx.x * 2;
    const int rowB = rowA + 1;
    const int tid = threadIdx.x;
    const int wid = tid >> 5, lid = tid & 31;
    const uint4* eA = reinterpret_cast<const uint4*>(&g_est[(size_t)rowA * NB]);
    const uint4* eB = reinterpret_cast<const uint4*>(&g_est[(size_t)rowB * NB]);

    __shared__ float red[2][8];
    __shared__ int   cand[2][64];
    __shared__ int   ccount[2];
    __shared__ float arow[2][DDIM];

    uint4 vA0 = eA[tid];
    uint4 vA1 = eA[256 + tid];
    uint4 vB0 = eB[tid];
    uint4 vB1 = eB[256 + tid];
    float2 fA[8], fB[8];
    {
        const uint32_t* a0 = reinterpret_cast<const uint32_t*>(&vA0);
        const uint32_t* a1 = reinterpret_cast<const uint32_t*>(&vA1);
        const uint32_t* b0 = reinterpret_cast<const uint32_t*>(&vB0);
        const uint32_t* b1 = reinterpret_cast<const uint32_t*>(&vB1);
#pragma unroll
        for (int q = 0; q < 4; ++q) {
            fA[q]     = __half22float2(*reinterpret_cast<const __half2*>(&a0[q]));
            fA[4 + q] = __half22float2(*reinterpret_cast<const __half2*>(&a1[q]));
            fB[q]     = __half22float2(*reinterpret_cast<const __half2*>(&b0[q]));
            fB[4 + q] = __half22float2(*reinterpret_cast<const __half2*>(&b1[q]));
        }
    }
    float lminA = 3.0e38f, lminB = 3.0e38f;
#pragma unroll
    for (int q = 0; q < 8; ++q) {
        lminA = fminf(lminA, fminf(fA[q].x, fA[q].y));
        lminB = fminf(lminB, fminf(fB[q].x, fB[q].y));
    }
#pragma unroll
    for (int off = 16; off > 0; off >>= 1) {
        lminA = fminf(lminA, __shfl_xor_sync(0xFFFFFFFFu, lminA, off));
        lminB = fminf(lminB, __shfl_xor_sync(0xFFFFFFFFu, lminB, off));
    }
    if (lid == 0) { red[0][wid] = lminA; red[1][wid] = lminB; }
    if (tid == 0) { ccount[0] = 0; ccount[1] = 0; }
    __syncthreads();
    float rowminA = red[0][0], rowminB = red[1][0];
#pragma unroll
    for (int w = 1; w < 8; ++w) {
        rowminA = fminf(rowminA, red[0][w]);
        rowminB = fminf(rowminB, red[1][w]);
    }

    const float thrA = rowminA + MARGIN;
    const float thrB = rowminB + MARGIN;
#pragma unroll
    for (int q = 0; q < 8; ++q) {
        const int j = (q < 4) ? (tid * 8 + q * 2) : (2048 + tid * 8 + (q - 4) * 2);
        if (fA[q].x <= thrA && j != rowA) {
            int p = atomicAdd(&ccount[0], 1);
            if (p < 64) cand[0][p] = j;
        }
        if (fA[q].y <= thrA && j + 1 != rowA) {
            int p = atomicAdd(&ccount[0], 1);
            if (p < 64) cand[0][p] = j + 1;
        }
        if (fB[q].x <= thrB && j != rowB) {
            int p = atomicAdd(&ccount[1], 1);
            if (p < 64) cand[1][p] = j;
        }
        if (fB[q].y <= thrB && j + 1 != rowB) {
            int p = atomicAdd(&ccount[1], 1);
            if (p < 64) cand[1][p] = j + 1;
        }
    }
    for (int j = tid; j < DDIM; j += 256) {
        arow[0][j] = out[(size_t)rowA * OLD + j];
        arow[1][j] = out[(size_t)rowB * OLD + j];
    }
    __syncthreads();

#pragma unroll
    for (int r = 0; r < 2; ++r) {
        const int row = rowA + r;
        int nc = ccount[r]; if (nc > 64) nc = 64;
        unsigned long long best = ~0ull;
        for (int k = 0; k < nc; ++k) {
            const int j = cand[r][k];
            const float* prow = &out[(size_t)j * OLD + DDIM];
            float s = 0.f;
            for (int tt = tid; tt < DDIM; tt += 256) s = fmaf(arow[r][tt], prow[tt], s);
#pragma unroll
            for (int off = 16; off > 0; off >>= 1)
                s += __shfl_xor_sync(0xFFFFFFFFu, s, off);
            if (lid == 0) red[0][wid] = s;
            __syncthreads();
            if (tid == 0) {
                float dot = 0.f;
#pragma unroll
                for (int w = 0; w < 8; ++w) dot += red[0][w];
                float dist = fmaf(-2.0f, dot, g_p2[j]);
                unsigned long long pk =
                    ((unsigned long long)__float_as_uint(dist) << 32) | (unsigned)j;
                if (pk < best) best = pk;
            }
            __syncthreads();
        }
        if (tid == 0) g_idx[row] = (int)(unsigned)(best & 0xFFFFFFFFull);
    }
}

// ---------------------------------------------------------------------------
// Gather hard negatives: out[:, 2048:3072] = pos[argmin]
// ---------------------------------------------------------------------------
__global__ __launch_bounds__(256) void gather_kernel(float* __restrict__ out) {
    const int row = blockIdx.x;
    const int idx = g_idx[row];
    const float4* src = reinterpret_cast<const float4*>(out + (size_t)idx * OLD + DDIM);
    float4* dst = reinterpret_cast<float4*>(out + (size_t)row * OLD + 2 * DDIM);
    dst[threadIdx.x] = src[threadIdx.x];
}

// ---------------------------------------------------------------------------
extern "C" void kernel_launch(void* const* d_in, const int* in_sizes, int n_in,
                              void* d_out, int out_size) {
    (void)in_sizes; (void)n_in; (void)out_size;
    const float* ax   = (const float*)d_in[0];
    const float* px   = (const float*)d_in[1];
    const float* W    = (const float*)d_in[2];
    const float* bias = (const float*)d_in[3];
    float* out = (float*)d_out;

    cudaFuncSetAttribute(proj_mma_kernel,
                         cudaFuncAttributeMaxDynamicSharedMemorySize, PSMEM_BYTES);
    cudaFuncSetAttribute(dist_est_kernel,
                         cudaFuncAttributeMaxDynamicSharedMemorySize, DSMEM_BYTES);

    void* p2addr = nullptr;
    cudaGetSymbolAddress(&p2addr, g_p2);
    cudaMemsetAsync(p2addr, 0, NB * sizeof(float));

    split_x_kernel<<<dim3(NB * DDIM / (256 * 16), 2), 256>>>(ax, px);
    split_w_kernel<<<dim3(DDIM / 32, DDIM / 32), 256>>>(W);
    proj_mma_kernel<<<PROJ_GRID, 256, PSMEM_BYTES>>>(bias, out);
    dist_est_kernel<<<DIST_GRID, 256, DSMEM_BYTES>>>();
    refine_kernel<<<NB / 2, 256>>>(out);
    gather_kernel<<<NB, 256>>>(out);
}